// round 4
// baseline (speedup 1.0000x reference)
#include <cuda_runtime.h>
#include <cstdint>
#include <math.h>

#define T 8192
#define C 512
#define II 64
#define E 32
#define KFB (E/2)
#define FULLMASK 0xffffffffu
#define NEGC (-3.3895313892515355e+38f)

// ---------------- device scratch ----------------
__device__ float g_rw[T * E];
__device__ int   g_idx[E * T];
__device__ int   g_cnt[E];
__device__ float g_colnorm[E];
__device__ float g_sig[E];
__device__ float g_W1t[(size_t)E * II * C];   // [e][i][c]  K-major, tf32-rounded
__device__ float g_W2t[(size_t)E * C * II];   // [e][c][i]  K-major, tf32-rounded

// ---------------- helpers ----------------
__device__ __forceinline__ float to_tf32(float f) {
    uint32_t u;
    asm("cvt.rna.tf32.f32 %0, %1;" : "=r"(u) : "f"(f));
    return __uint_as_float(u);
}

__device__ __forceinline__ void mma16n8k8(float* d, const uint32_t* a, const uint32_t* b) {
    asm volatile(
        "mma.sync.aligned.m16n8k8.row.col.f32.tf32.tf32.f32 "
        "{%0,%1,%2,%3}, {%4,%5,%6,%7}, {%8,%9}, {%0,%1,%2,%3};"
        : "+f"(d[0]), "+f"(d[1]), "+f"(d[2]), "+f"(d[3])
        : "r"(a[0]), "r"(a[1]), "r"(a[2]), "r"(a[3]), "r"(b[0]), "r"(b[1]));
}

__device__ __forceinline__ float gelu_exact(float v) {
    return 0.5f * v * (1.0f + erff(v * 0.70710678118654752f));
}

// ---------------- kernel 0: prep ----------------
__global__ void prep_kernel(const float* __restrict__ sim, const float* __restrict__ gates) {
    int w = threadIdx.x >> 5;
    int lane = threadIdx.x & 31;
    float s = 0.f;
    for (int c = lane; c < C; c += 32) {
        float v = sim[c * E + w];
        s = fmaf(v, v, s);
    }
    #pragma unroll
    for (int o = 16; o; o >>= 1) s += __shfl_xor_sync(FULLMASK, s, o);
    if (lane == 0) {
        g_colnorm[w] = fmaxf(sqrtf(s), 1e-12f);
        g_sig[w]     = 1.f / (1.f + expf(-gates[w]));
        g_cnt[w]     = 0;
    }
}

// ---------------- weight transposes (K-major + tf32 rounding) ----------------
__global__ __launch_bounds__(256) void transpose_w1(const float* __restrict__ W1) {
    __shared__ float t[32][33];
    int e = blockIdx.z, c0 = blockIdx.x * 32, i0 = blockIdx.y * 32;
    int tx = threadIdx.x & 31, ty = threadIdx.x >> 5;
    #pragma unroll
    for (int j = 0; j < 32; j += 8)
        t[ty + j][tx] = W1[((size_t)e * C + c0 + ty + j) * II + i0 + tx];
    __syncthreads();
    #pragma unroll
    for (int j = 0; j < 32; j += 8)
        g_W1t[((size_t)e * II + i0 + ty + j) * C + c0 + tx] = to_tf32(t[tx][ty + j]);
}
__global__ __launch_bounds__(256) void transpose_w2(const float* __restrict__ W2) {
    __shared__ float t[32][33];
    int e = blockIdx.z, i0 = blockIdx.x * 32, c0 = blockIdx.y * 32;
    int tx = threadIdx.x & 31, ty = threadIdx.x >> 5;
    #pragma unroll
    for (int j = 0; j < 32; j += 8)
        t[ty + j][tx] = W2[((size_t)e * II + i0 + ty + j) * C + c0 + tx];
    __syncthreads();
    #pragma unroll
    for (int j = 0; j < 32; j += 8)
        g_W2t[((size_t)e * C + c0 + ty + j) * II + i0 + tx] = to_tf32(t[tx][ty + j]);
}

// ---------------- kernel 1: gating (4 tokens per warp) ----------------
__global__ __launch_bounds__(256) void gating_kernel(
    const float* __restrict__ x, const float* __restrict__ sim,
    float* __restrict__ pre_out, float* __restrict__ mask_out) {
    __shared__ float s_x[32 * C];            // 64KB: 32 token rows
    __shared__ unsigned char s_act[32][E];

    int tid = threadIdx.x, w = tid >> 5, lane = tid & 31;
    int t0 = blockIdx.x * 32;

    const float4* xb = (const float4*)(x + (size_t)t0 * C);
    float4* sx4 = (float4*)s_x;
    #pragma unroll
    for (int p = 0; p < 16; p++) sx4[tid + p * 256] = xb[tid + p * 256];
    __syncthreads();

    // norms for this warp's 4 tokens
    float xn[4];
    #pragma unroll
    for (int j = 0; j < 4; j++) {
        const float* row = s_x + (w * 4 + j) * C;
        float s = 0.f;
        #pragma unroll 4
        for (int c = lane; c < C; c += 32) { float v = row[c]; s = fmaf(v, v, s); }
        #pragma unroll
        for (int o = 16; o; o >>= 1) s += __shfl_xor_sync(FULLMASK, s, o);
        xn[j] = fmaxf(sqrtf(s), 1e-12f);
    }

    // dots: 1 LDG amortized over 4 tokens; lane == expert
    const float* r0 = s_x + (w * 4 + 0) * C;
    const float* r1 = s_x + (w * 4 + 1) * C;
    const float* r2 = s_x + (w * 4 + 2) * C;
    const float* r3 = s_x + (w * 4 + 3) * C;
    float a0 = 0.f, a1 = 0.f, a2 = 0.f, a3 = 0.f;
    #pragma unroll 4
    for (int c = 0; c < C; c++) {
        float sv = __ldg(&sim[c * E + lane]);
        a0 = fmaf(r0[c], sv, a0);
        a1 = fmaf(r1[c], sv, a1);
        a2 = fmaf(r2[c], sv, a2);
        a3 = fmaf(r3[c], sv, a3);
    }
    float accv[4] = {a0, a1, a2, a3};

    float cn = g_colnorm[lane], sg = g_sig[lane];
    #pragma unroll 1
    for (int j = 0; j < 4; j++) {
        int t = t0 + w * 4 + j;
        float logit = accv[j] / (xn[j] * cn);
        float pre   = logit - sg;
        float gated = fmaxf(pre, 0.f);

        unsigned act = __ballot_sync(FULLMASK, gated > 0.f);
        float maskv;
        if (act == 0u) {
            int rank = 0;
            #pragma unroll
            for (int jj = 0; jj < 32; jj++) {
                float lj = __shfl_sync(FULLMASK, logit, jj);
                rank += (lj > logit) || (lj == logit && jj < lane);
            }
            maskv = (rank < KFB) ? 1.f : 0.f;
        } else {
            maskv = (gated > 0.f) ? 1.f : 0.f;
        }

        float maskedv = (maskv > 0.f) ? gated : NEGC;
        float m = maskedv;
        #pragma unroll
        for (int o = 16; o; o >>= 1) m = fmaxf(m, __shfl_xor_sync(FULLMASK, m, o));
        float p = expf(maskedv - m);
        float ss = p;
        #pragma unroll
        for (int o = 16; o; o >>= 1) ss += __shfl_xor_sync(FULLMASK, ss, o);

        pre_out[t * E + lane]  = pre;
        mask_out[t * E + lane] = maskv;
        g_rw[t * E + lane]     = p / ss;
        s_act[w * 4 + j][lane] = (maskv > 0.f) ? 1 : 0;
    }
    __syncthreads();

    if (tid < E) {
        int e = tid;
        int cntl = 0;
        #pragma unroll
        for (int s2 = 0; s2 < 32; s2++) cntl += s_act[s2][e];
        if (cntl > 0) {
            int base = atomicAdd(&g_cnt[e], cntl);
            for (int s2 = 0; s2 < 32; s2++)
                if (s_act[s2][e]) g_idx[e * T + base++] = t0 + s2;
        }
    }
}

// ---------------- fused expert MLP: feo = (gelu(Xg @ W1t^T)) @ W2t^T ----------------
// block = (128-token tile, expert). Phase1: K=512 in 8 chunks -> H (in SMEM).
// Phase2: 4 n-chunks of 128 cols, K=64 -> scatter feo.
#define MS 68
#define EM_OFF_RW  512
#define EM_OFF_A   1024
#define EM_OFF_B   (1024 + 128 * MS * 4)
#define EM_SMEM    (EM_OFF_B + 128 * MS * 4)

__global__ __launch_bounds__(256) void expert_mlp(const float* __restrict__ x,
                                                  float* __restrict__ feo) {
    int e = blockIdx.y;
    int cnt = g_cnt[e];
    int m0 = blockIdx.x * 128;
    if (m0 >= cnt) return;

    extern __shared__ char smem[];
    int* toks = (int*)smem;
    float* As = (float*)(smem + EM_OFF_A);   // X chunks, later H (128 x 64, stride MS)
    float* Bs = (float*)(smem + EM_OFF_B);   // W1 chunk / W2 chunk

    int tid = threadIdx.x, wid = tid >> 5, lane = tid & 31;
    if (tid < 128) toks[tid] = (m0 + tid < cnt) ? g_idx[e * T + m0 + tid] : -1;
    __syncthreads();

    int warpM = wid >> 1, warpN = wid & 1;
    int rbase = warpM * 32;
    int lr = lane >> 2, lc = lane & 3;

    // ---------- phase 1: H = gelu(Xg @ W1^T), warp tile 32x32 ----------
    {
        int nbase = warpN * 32;
        float d[2][4][4];
        #pragma unroll
        for (int mt = 0; mt < 2; mt++)
            #pragma unroll
            for (int nt = 0; nt < 4; nt++)
                #pragma unroll
                for (int i = 0; i < 4; i++) d[mt][nt][i] = 0.f;

        for (int kc = 0; kc < 8; kc++) {
            #pragma unroll
            for (int p = 0; p < 8; p++) {
                int fi = tid + (p << 8);
                int r = fi >> 4, q = fi & 15;
                int tok = toks[r];
                float4 v = make_float4(0.f, 0.f, 0.f, 0.f);
                if (tok >= 0) v = *(const float4*)(x + (size_t)tok * C + kc * 64 + q * 4);
                float4 u = make_float4(to_tf32(v.x), to_tf32(v.y), to_tf32(v.z), to_tf32(v.w));
                *(float4*)(As + r * MS + q * 4) = u;
            }
            #pragma unroll
            for (int p = 0; p < 4; p++) {
                int fi = tid + (p << 8);
                int i = fi >> 4, q = fi & 15;
                float4 v = *(const float4*)(g_W1t + ((size_t)e * II + i) * C + kc * 64 + q * 4);
                *(float4*)(Bs + i * MS + q * 4) = v;
            }
            __syncthreads();

            #pragma unroll
            for (int ks = 0; ks < 8; ks++) {
                int k0 = ks * 8;
                uint32_t afr[2][4], bfr[4][2];
                #pragma unroll
                for (int mt = 0; mt < 2; mt++) {
                    int row = rbase + mt * 16 + lr;
                    afr[mt][0] = __float_as_uint(As[row * MS + k0 + lc]);
                    afr[mt][1] = __float_as_uint(As[(row + 8) * MS + k0 + lc]);
                    afr[mt][2] = __float_as_uint(As[row * MS + k0 + lc + 4]);
                    afr[mt][3] = __float_as_uint(As[(row + 8) * MS + k0 + lc + 4]);
                }
                #pragma unroll
                for (int nt = 0; nt < 4; nt++) {
                    int col = nbase + nt * 8 + lr;
                    bfr[nt][0] = __float_as_uint(Bs[col * MS + k0 + lc]);
                    bfr[nt][1] = __float_as_uint(Bs[col * MS + k0 + lc + 4]);
                }
                #pragma unroll
                for (int mt = 0; mt < 2; mt++)
                    #pragma unroll
                    for (int nt = 0; nt < 4; nt++)
                        mma16n8k8(d[mt][nt], afr[mt], bfr[nt]);
            }
            __syncthreads();
        }

        // H epilogue -> As (gelu + tf32 round); safe: all mma done, all threads synced
        #pragma unroll
        for (int mt = 0; mt < 2; mt++) {
            int r0 = rbase + mt * 16 + lr;
            #pragma unroll
            for (int nt = 0; nt < 4; nt++) {
                int col = nbase + nt * 8 + lc * 2;
                As[r0 * MS + col]           = to_tf32(gelu_exact(d[mt][nt][0]));
                As[r0 * MS + col + 1]       = to_tf32(gelu_exact(d[mt][nt][1]));
                As[(r0 + 8) * MS + col]     = to_tf32(gelu_exact(d[mt][nt][2]));
                As[(r0 + 8) * MS + col + 1] = to_tf32(gelu_exact(d[mt][nt][3]));
            }
        }
    }

    // ---------- phase 2: Y = H @ W2^T over 4 n-chunks, warp tile 32x64 ----------
    int nbase2 = warpN * 64;
    for (int nc = 0; nc < 4; nc++) {
        #pragma unroll
        for (int p = 0; p < 8; p++) {
            int fi = tid + (p << 8);
            int n = fi >> 4, q = fi & 15;
            float4 v = *(const float4*)(g_W2t + ((size_t)e * C + nc * 128 + n) * II + q * 4);
            *(float4*)(Bs + n * MS + q * 4) = v;
        }
        __syncthreads();   // also orders H writes (nc==0) / prior reads before reuse

        float d2[2][8][4];
        #pragma unroll
        for (int mt = 0; mt < 2; mt++)
            #pragma unroll
            for (int nt = 0; nt < 8; nt++)
                #pragma unroll
                for (int i = 0; i < 4; i++) d2[mt][nt][i] = 0.f;

        #pragma unroll
        for (int ks = 0; ks < 8; ks++) {
            int k0 = ks * 8;
            uint32_t afr[2][4], bfr[8][2];
            #pragma unroll
            for (int mt = 0; mt < 2; mt++) {
                int row = rbase + mt * 16 + lr;
                afr[mt][0] = __float_as_uint(As[row * MS + k0 + lc]);
                afr[mt][1] = __float_as_uint(As[(row + 8) * MS + k0 + lc]);
                afr[mt][2] = __float_as_uint(As[row * MS + k0 + lc + 4]);
                afr[mt][3] = __float_as_uint(As[(row + 8) * MS + k0 + lc + 4]);
            }
            #pragma unroll
            for (int nt = 0; nt < 8; nt++) {
                int col = nbase2 + nt * 8 + lr;
                bfr[nt][0] = __float_as_uint(Bs[col * MS + k0 + lc]);
                bfr[nt][1] = __float_as_uint(Bs[col * MS + k0 + lc + 4]);
            }
            #pragma unroll
            for (int mt = 0; mt < 2; mt++)
                #pragma unroll
                for (int nt = 0; nt < 8; nt++)
                    mma16n8k8(d2[mt][nt], afr[mt], bfr[nt]);
        }

        #pragma unroll
        for (int mt = 0; mt < 2; mt++) {
            int s0 = rbase + mt * 16 + lr, s1 = s0 + 8;
            int tok0 = toks[s0], tok1 = toks[s1];
            #pragma unroll
            for (int nt = 0; nt < 8; nt++) {
                int col = nc * 128 + nbase2 + nt * 8 + lc * 2;
                if (tok0 >= 0)
                    *(float2*)&feo[((size_t)tok0 * E + e) * C + col] =
                        make_float2(d2[mt][nt][0], d2[mt][nt][1]);
                if (tok1 >= 0)
                    *(float2*)&feo[((size_t)tok1 * E + e) * C + col] =
                        make_float2(d2[mt][nt][2], d2[mt][nt][3]);
            }
        }
        __syncthreads();
    }
}

// ---------------- zero inactive feo rows (overlapped with expert_mlp) ----------------
__global__ __launch_bounds__(128) void zero_inactive(const float* __restrict__ maskp,
                                                     float* __restrict__ feo) {
    int t = blockIdx.x;
    int e = threadIdx.x >> 2, q = threadIdx.x & 3;
    if (maskp[(size_t)t * E + e] > 0.f) return;
    float4* row = (float4*)&feo[((size_t)t * E + e) * C];
    float4 z = make_float4(0.f, 0.f, 0.f, 0.f);
    #pragma unroll
    for (int i = 0; i < 32; i++) row[(i << 2) + q] = z;
}

// ---------------- final reduce: final = sum_e rw * feo (active rows only) ----------------
__global__ __launch_bounds__(128) void final_reduce(
    const float* __restrict__ maskp, const float* __restrict__ feo,
    float* __restrict__ final_out) {
    int t = blockIdx.x;
    int tid = threadIdx.x;
    float4 acc = make_float4(0.f, 0.f, 0.f, 0.f);
    #pragma unroll 1
    for (int e = 0; e < E; e++) {
        if (maskp[(size_t)t * E + e] > 0.f) {
            float wv = g_rw[t * E + e];
            float4 v = ((const float4*)&feo[((size_t)t * E + e) * C])[tid];
            acc.x = fmaf(wv, v.x, acc.x);
            acc.y = fmaf(wv, v.y, acc.y);
            acc.z = fmaf(wv, v.z, acc.z);
            acc.w = fmaf(wv, v.w, acc.w);
        }
    }
    ((float4*)&final_out[(size_t)t * C])[tid] = acc;
}

// ---------------- launch ----------------
extern "C" void kernel_launch(void* const* d_in, const int* in_sizes, int n_in,
                              void* d_out, int out_size) {
    const float* x     = (const float*)d_in[0];
    const float* sim   = (const float*)d_in[1];
    const float* gates = (const float*)d_in[2];
    const float* W1    = (const float*)d_in[3];
    const float* W2    = (const float*)d_in[4];

    float* out       = (float*)d_out;
    float* final_out = out;
    float* feo       = out + (size_t)T * C;
    float* pre       = feo + (size_t)T * E * C;
    float* maskp     = pre + (size_t)T * E;

    cudaFuncSetAttribute(expert_mlp, cudaFuncAttributeMaxDynamicSharedMemorySize, EM_SMEM);

    cudaStream_t s2;
    cudaEvent_t ev1, ev2;
    cudaStreamCreateWithFlags(&s2, cudaStreamNonBlocking);
    cudaEventCreateWithFlags(&ev1, cudaEventDisableTiming);
    cudaEventCreateWithFlags(&ev2, cudaEventDisableTiming);

    prep_kernel<<<1, 1024>>>(sim, gates);
    transpose_w1<<<dim3(C / 32, II / 32, E), 256>>>(W1);
    transpose_w2<<<dim3(II / 32, C / 32, E), 256>>>(W2);
    gating_kernel<<<T / 32, 256>>>(x, sim, pre, maskp);

    // fork: zero inactive feo rows concurrently with expert compute (disjoint rows)
    cudaEventRecord(ev1, 0);
    cudaStreamWaitEvent(s2, ev1, 0);
    zero_inactive<<<T, 128, 0, s2>>>(maskp, feo);
    cudaEventRecord(ev2, s2);

    expert_mlp<<<dim3(T / 128, E), 256, EM_SMEM>>>(x, feo);

    cudaStreamWaitEvent(0, ev2, 0);
    final_reduce<<<T, 128>>>(maskp, feo, final_out);
}

// round 5
// speedup vs baseline: 1.0914x; 1.0914x over previous
#include <cuda_runtime.h>
#include <cstdint>
#include <math.h>

#define T 8192
#define C 512
#define II 64
#define E 32
#define KFB (E/2)
#define FULLMASK 0xffffffffu
#define NEGC (-3.3895313892515355e+38f)

// ---------------- device scratch ----------------
__device__ float g_rw[T * E];
__device__ int   g_idx[E * T];        // per-expert active token lists
__device__ int   g_iidx[E * T];       // per-expert inactive token lists
__device__ int   g_cnt[E];
__device__ int   g_icnt[E];
__device__ float g_colnorm[E];
__device__ float g_sig[E];
__device__ float g_W1t[(size_t)E * II * C];   // [e][i][pk]  K-major, tf32, perm per 8-k group
__device__ float g_W2t[(size_t)E * C * II];   // [e][c][pk]  K-major, tf32, perm per 8-k group

// permuted column within each 8-k group: kk -> ((kk&3)<<1)|(kk>>2)
#define PCOL(k) (((k) & ~7) | ((((k) & 3) << 1) | (((k) >> 2) & 1)))

// ---------------- helpers ----------------
__device__ __forceinline__ float to_tf32(float f) {
    uint32_t u;
    asm("cvt.rna.tf32.f32 %0, %1;" : "=r"(u) : "f"(f));
    return __uint_as_float(u);
}

__device__ __forceinline__ void mma16n8k8(float* d, const uint32_t* a, const uint32_t* b) {
    asm volatile(
        "mma.sync.aligned.m16n8k8.row.col.f32.tf32.tf32.f32 "
        "{%0,%1,%2,%3}, {%4,%5,%6,%7}, {%8,%9}, {%0,%1,%2,%3};"
        : "+f"(d[0]), "+f"(d[1]), "+f"(d[2]), "+f"(d[3])
        : "r"(a[0]), "r"(a[1]), "r"(a[2]), "r"(a[3]), "r"(b[0]), "r"(b[1]));
}

__device__ __forceinline__ float gelu_exact(float v) {
    return 0.5f * v * (1.0f + erff(v * 0.70710678118654752f));
}

// ---------------- kernel 0: prep ----------------
__global__ void prep_kernel(const float* __restrict__ sim, const float* __restrict__ gates) {
    int w = threadIdx.x >> 5;
    int lane = threadIdx.x & 31;
    float s = 0.f;
    for (int c = lane; c < C; c += 32) {
        float v = sim[c * E + w];
        s = fmaf(v, v, s);
    }
    #pragma unroll
    for (int o = 16; o; o >>= 1) s += __shfl_xor_sync(FULLMASK, s, o);
    if (lane == 0) {
        g_colnorm[w] = fmaxf(sqrtf(s), 1e-12f);
        g_sig[w]     = 1.f / (1.f + expf(-gates[w]));
        g_cnt[w]     = 0;
        g_icnt[w]    = 0;
    }
}

// ---------------- weight transposes (K-major + tf32 + fragment permutation) ----------------
__global__ __launch_bounds__(256) void transpose_w1(const float* __restrict__ W1) {
    __shared__ float t[32][33];
    int e = blockIdx.z, c0 = blockIdx.x * 32, i0 = blockIdx.y * 32;
    int tx = threadIdx.x & 31, ty = threadIdx.x >> 5;
    #pragma unroll
    for (int j = 0; j < 32; j += 8)
        t[ty + j][tx] = W1[((size_t)e * C + c0 + ty + j) * II + i0 + tx];
    __syncthreads();
    #pragma unroll
    for (int j = 0; j < 32; j += 8)
        g_W1t[((size_t)e * II + i0 + ty + j) * C + PCOL(c0 + tx)] = to_tf32(t[tx][ty + j]);
}
__global__ __launch_bounds__(256) void transpose_w2(const float* __restrict__ W2) {
    __shared__ float t[32][33];
    int e = blockIdx.z, i0 = blockIdx.x * 32, c0 = blockIdx.y * 32;
    int tx = threadIdx.x & 31, ty = threadIdx.x >> 5;
    #pragma unroll
    for (int j = 0; j < 32; j += 8)
        t[ty + j][tx] = W2[((size_t)e * II + i0 + ty + j) * C + c0 + tx];
    __syncthreads();
    #pragma unroll
    for (int j = 0; j < 32; j += 8)
        g_W2t[((size_t)e * C + c0 + ty + j) * II + PCOL(i0 + tx)] = to_tf32(t[tx][ty + j]);
}

// ---------------- kernel 1: gating (R3 warp-per-token + dual lists) ----------------
__global__ __launch_bounds__(256) void gating_kernel(
    const float* __restrict__ x, const float* __restrict__ sim,
    float* __restrict__ pre_out, float* __restrict__ mask_out) {
    __shared__ float s_x[8 * C];
    __shared__ unsigned char s_act[8][E];

    int tid = threadIdx.x;
    int w = tid >> 5;
    int lane = tid & 31;
    int t0 = blockIdx.x * 8;
    int t = t0 + w;

    const float* xbase = x + (size_t)t0 * C;
    #pragma unroll
    for (int p = 0; p < 16; p++) s_x[tid + p * 256] = xbase[tid + p * 256];
    __syncthreads();

    const float* xw = s_x + w * C;
    float acc = 0.f, nsq = 0.f;
    #pragma unroll 8
    for (int c = 0; c < C; c++) {
        float xc = xw[c];
        acc = fmaf(xc, __ldg(&sim[c * E + lane]), acc);
        nsq = fmaf(xc, xc, nsq);
    }

    float xnorm = fmaxf(sqrtf(nsq), 1e-12f);
    float logit = acc / (xnorm * g_colnorm[lane]);
    float pre   = logit - g_sig[lane];
    float gated = fmaxf(pre, 0.f);

    unsigned act = __ballot_sync(FULLMASK, gated > 0.f);
    float maskv;
    if (act == 0u) {
        int rank = 0;
        #pragma unroll
        for (int j = 0; j < 32; j++) {
            float lj = __shfl_sync(FULLMASK, logit, j);
            rank += (lj > logit) || (lj == logit && j < lane);
        }
        maskv = (rank < KFB) ? 1.f : 0.f;
    } else {
        maskv = (gated > 0.f) ? 1.f : 0.f;
    }

    float maskedv = (maskv > 0.f) ? gated : NEGC;
    float m = maskedv;
    #pragma unroll
    for (int o = 16; o; o >>= 1) m = fmaxf(m, __shfl_xor_sync(FULLMASK, m, o));
    float p = expf(maskedv - m);
    float ssum = p;
    #pragma unroll
    for (int o = 16; o; o >>= 1) ssum += __shfl_xor_sync(FULLMASK, ssum, o);
    float rw = p / ssum;

    pre_out[t * E + lane]  = pre;
    mask_out[t * E + lane] = maskv;
    g_rw[t * E + lane]     = rw;
    s_act[w][lane] = (maskv > 0.f) ? 1 : 0;
    __syncthreads();

    if (tid < E) {
        int e = tid;
        int cntl = 0;
        #pragma unroll
        for (int s2 = 0; s2 < 8; s2++) cntl += s_act[s2][e];
        if (cntl > 0) {
            int base = atomicAdd(&g_cnt[e], cntl);
            for (int s2 = 0; s2 < 8; s2++)
                if (s_act[s2][e]) g_idx[e * T + base++] = t0 + s2;
        }
        if (cntl < 8) {
            int ibase = atomicAdd(&g_icnt[e], 8 - cntl);
            for (int s2 = 0; s2 < 8; s2++)
                if (!s_act[s2][e]) g_iidx[e * T + ibase++] = t0 + s2;
        }
    }
}

// ---------------- fused expert MLP + inactive zeroing ----------------
// grid = (T/128 + 1, E). Blocks [0, cntB): compute feo for active tiles.
// Blocks [cntB, ...): zero inactive rows (overlaps with compute blocks).
#define MS 72
#define EM_OFF_A   1024
#define EM_OFF_B   (1024 + 128 * MS * 4)
#define EM_SMEM    (EM_OFF_B + 128 * MS * 4)

__global__ __launch_bounds__(256) void expert_mlp(const float* __restrict__ x,
                                                  float* __restrict__ feo) {
    int e = blockIdx.y;
    int cnt = g_cnt[e];
    int cntB = (cnt + 127) >> 7;
    int tid = threadIdx.x;

    extern __shared__ char smem[];
    int* toks = (int*)smem;

    if ((int)blockIdx.x >= cntB) {
        // ---------- zero path: inactive rows ----------
        int icnt = g_icnt[e];
        int zi0 = ((int)blockIdx.x - cntB) * 128;
        if (zi0 >= icnt) return;
        int nrows = min(128, icnt - zi0);
        if (tid < nrows) toks[tid] = g_iidx[e * T + zi0 + tid];
        __syncthreads();
        float4 z = make_float4(0.f, 0.f, 0.f, 0.f);
        for (int j = tid; j < nrows * 128; j += 256) {
            int r = j >> 7, q = j & 127;
            ((float4*)&feo[((size_t)toks[r] * E + e) * C])[q] = z;
        }
        return;
    }

    // ---------- compute path ----------
    int m0 = blockIdx.x * 128;
    float* As = (float*)(smem + EM_OFF_A);   // X chunks / H (128 x 64, stride MS, permuted)
    float* Bs = (float*)(smem + EM_OFF_B);   // W chunk (permuted)

    int wid = tid >> 5, lane = tid & 31;
    if (tid < 128) toks[tid] = (m0 + tid < cnt) ? g_idx[e * T + m0 + tid] : -1;
    __syncthreads();

    int warpM = wid >> 1, warpN = wid & 1;
    int rbase = warpM * 32;
    int lr = lane >> 2, lc = lane & 3;

    // ---------- phase 1: H = gelu(Xg @ W1^T), warp tile 32x32 ----------
    {
        int nbase = warpN * 32;
        float d[2][4][4];
        #pragma unroll
        for (int mt = 0; mt < 2; mt++)
            #pragma unroll
            for (int nt = 0; nt < 4; nt++)
                #pragma unroll
                for (int i = 0; i < 4; i++) d[mt][nt][i] = 0.f;

        for (int kc = 0; kc < 8; kc++) {
            // stage X chunk (128 rows x 64 k), tf32-rounded, perm per 8-k group
            #pragma unroll
            for (int p = 0; p < 4; p++) {
                int gi = tid + (p << 8);          // 0..1023 (row, group)
                int r = gi >> 3, g = gi & 7;
                int tok = toks[r];
                float4 f0 = make_float4(0.f, 0.f, 0.f, 0.f), f1 = f0;
                if (tok >= 0) {
                    const float* xp = x + (size_t)tok * C + kc * 64 + g * 8;
                    f0 = *(const float4*)xp;
                    f1 = *(const float4*)(xp + 4);
                }
                float2* dst = (float2*)(As + r * MS + g * 8);
                dst[0] = make_float2(to_tf32(f0.x), to_tf32(f1.x));
                dst[1] = make_float2(to_tf32(f0.y), to_tf32(f1.y));
                dst[2] = make_float2(to_tf32(f0.z), to_tf32(f1.z));
                dst[3] = make_float2(to_tf32(f0.w), to_tf32(f1.w));
            }
            // stage W1 chunk (64 rows x 64 k), pre-permuted -> straight copy
            #pragma unroll
            for (int p = 0; p < 4; p++) {
                int fi = tid + (p << 8);
                int i = fi >> 4, q = fi & 15;
                float4 v = *(const float4*)(g_W1t + ((size_t)e * II + i) * C + kc * 64 + q * 4);
                *(float4*)(Bs + i * MS + q * 4) = v;
            }
            __syncthreads();

            #pragma unroll
            for (int ks = 0; ks < 8; ks++) {
                int k0 = ks * 8;
                uint32_t afr[2][4], bfr[4][2];
                #pragma unroll
                for (int mt = 0; mt < 2; mt++) {
                    int row = rbase + mt * 16 + lr;
                    float2 pa0 = *(float2*)(As + row * MS + k0 + lc * 2);
                    float2 pa1 = *(float2*)(As + (row + 8) * MS + k0 + lc * 2);
                    afr[mt][0] = __float_as_uint(pa0.x);
                    afr[mt][1] = __float_as_uint(pa1.x);
                    afr[mt][2] = __float_as_uint(pa0.y);
                    afr[mt][3] = __float_as_uint(pa1.y);
                }
                #pragma unroll
                for (int nt = 0; nt < 4; nt++) {
                    int col = nbase + nt * 8 + lr;
                    float2 pb = *(float2*)(Bs + col * MS + k0 + lc * 2);
                    bfr[nt][0] = __float_as_uint(pb.x);
                    bfr[nt][1] = __float_as_uint(pb.y);
                }
                #pragma unroll
                for (int mt = 0; mt < 2; mt++)
                    #pragma unroll
                    for (int nt = 0; nt < 4; nt++)
                        mma16n8k8(d[mt][nt], afr[mt], bfr[nt]);
            }
            __syncthreads();
        }

        // H epilogue -> As in permuted layout
        int pos0 = ((lc & 1) << 2) | (lc >> 1);   // perm(2*lc)
        #pragma unroll
        for (int mt = 0; mt < 2; mt++) {
            int r0 = rbase + mt * 16 + lr;
            #pragma unroll
            for (int nt = 0; nt < 4; nt++) {
                int base = nbase + nt * 8;
                As[r0 * MS + base + pos0]           = to_tf32(gelu_exact(d[mt][nt][0]));
                As[r0 * MS + base + pos0 + 2]       = to_tf32(gelu_exact(d[mt][nt][1]));
                As[(r0 + 8) * MS + base + pos0]     = to_tf32(gelu_exact(d[mt][nt][2]));
                As[(r0 + 8) * MS + base + pos0 + 2] = to_tf32(gelu_exact(d[mt][nt][3]));
            }
        }
    }

    // ---------- phase 2: Y = H @ W2^T over 4 n-chunks, warp tile 32x64 ----------
    int nbase2 = warpN * 64;
    for (int nc = 0; nc < 4; nc++) {
        #pragma unroll
        for (int p = 0; p < 8; p++) {
            int fi = tid + (p << 8);
            int n = fi >> 4, q = fi & 15;
            float4 v = *(const float4*)(g_W2t + ((size_t)e * C + nc * 128 + n) * II + q * 4);
            *(float4*)(Bs + n * MS + q * 4) = v;
        }
        __syncthreads();   // orders H writes (nc==0) and Bs reuse

        float d2[2][8][4];
        #pragma unroll
        for (int mt = 0; mt < 2; mt++)
            #pragma unroll
            for (int nt = 0; nt < 8; nt++)
                #pragma unroll
                for (int i = 0; i < 4; i++) d2[mt][nt][i] = 0.f;

        #pragma unroll
        for (int ks = 0; ks < 8; ks++) {
            int k0 = ks * 8;
            uint32_t afr[2][4], bfr[8][2];
            #pragma unroll
            for (int mt = 0; mt < 2; mt++) {
                int row = rbase + mt * 16 + lr;
                float2 pa0 = *(float2*)(As + row * MS + k0 + lc * 2);
                float2 pa1 = *(float2*)(As + (row + 8) * MS + k0 + lc * 2);
                afr[mt][0] = __float_as_uint(pa0.x);
                afr[mt][1] = __float_as_uint(pa1.x);
                afr[mt][2] = __float_as_uint(pa0.y);
                afr[mt][3] = __float_as_uint(pa1.y);
            }
            #pragma unroll
            for (int nt = 0; nt < 8; nt++) {
                int col = nbase2 + nt * 8 + lr;
                float2 pb = *(float2*)(Bs + col * MS + k0 + lc * 2);
                bfr[nt][0] = __float_as_uint(pb.x);
                bfr[nt][1] = __float_as_uint(pb.y);
            }
            #pragma unroll
            for (int mt = 0; mt < 2; mt++)
                #pragma unroll
                for (int nt = 0; nt < 8; nt++)
                    mma16n8k8(d2[mt][nt], afr[mt], bfr[nt]);
        }

        #pragma unroll
        for (int mt = 0; mt < 2; mt++) {
            int s0 = rbase + mt * 16 + lr, s1 = s0 + 8;
            int tok0 = toks[s0], tok1 = toks[s1];
            #pragma unroll
            for (int nt = 0; nt < 8; nt++) {
                int col = nc * 128 + nbase2 + nt * 8 + lc * 2;
                if (tok0 >= 0)
                    *(float2*)&feo[((size_t)tok0 * E + e) * C + col] =
                        make_float2(d2[mt][nt][0], d2[mt][nt][1]);
                if (tok1 >= 0)
                    *(float2*)&feo[((size_t)tok1 * E + e) * C + col] =
                        make_float2(d2[mt][nt][2], d2[mt][nt][3]);
            }
        }
        __syncthreads();
    }
}

// ---------------- final reduce: final = sum_e rw * feo (active rows only) ----------------
__global__ __launch_bounds__(128) void final_reduce(
    const float* __restrict__ maskp, const float* __restrict__ feo,
    float* __restrict__ final_out) {
    int t = blockIdx.x;
    int tid = threadIdx.x;
    float4 acc = make_float4(0.f, 0.f, 0.f, 0.f);
    #pragma unroll 1
    for (int e = 0; e < E; e++) {
        if (maskp[(size_t)t * E + e] > 0.f) {
            float wv = g_rw[t * E + e];
            float4 v = ((const float4*)&feo[((size_t)t * E + e) * C])[tid];
            acc.x = fmaf(wv, v.x, acc.x);
            acc.y = fmaf(wv, v.y, acc.y);
            acc.z = fmaf(wv, v.z, acc.z);
            acc.w = fmaf(wv, v.w, acc.w);
        }
    }
    ((float4*)&final_out[(size_t)t * C])[tid] = acc;
}

// ---------------- launch ----------------
extern "C" void kernel_launch(void* const* d_in, const int* in_sizes, int n_in,
                              void* d_out, int out_size) {
    const float* x     = (const float*)d_in[0];
    const float* sim   = (const float*)d_in[1];
    const float* gates = (const float*)d_in[2];
    const float* W1    = (const float*)d_in[3];
    const float* W2    = (const float*)d_in[4];

    float* out       = (float*)d_out;
    float* final_out = out;
    float* feo       = out + (size_t)T * C;
    float* pre       = feo + (size_t)T * E * C;
    float* maskp     = pre + (size_t)T * E;

    cudaFuncSetAttribute(expert_mlp, cudaFuncAttributeMaxDynamicSharedMemorySize, EM_SMEM);

    prep_kernel<<<1, 1024>>>(sim, gates);
    transpose_w1<<<dim3(C / 32, II / 32, E), 256>>>(W1);
    transpose_w2<<<dim3(II / 32, C / 32, E), 256>>>(W2);
    gating_kernel<<<T / 8, 256>>>(x, sim, pre, maskp);
    expert_mlp<<<dim3(T / 128 + 1, E), 256, EM_SMEM>>>(x, feo);
    final_reduce<<<T, 128>>>(maskp, feo, final_out);
}

// round 6
// speedup vs baseline: 1.2357x; 1.1322x over previous
#include <cuda_runtime.h>
#include <cstdint>
#include <math.h>

#define T 8192
#define C 512
#define II 64
#define E 32
#define KFB (E/2)
#define FULLMASK 0xffffffffu
#define NEGC (-3.3895313892515355e+38f)

// ---------------- device scratch ----------------
__device__ float g_rw[T * E];
__device__ int   g_idx[E * T];        // per-expert active token lists
__device__ int   g_iidx[E * T];       // per-expert inactive token lists
__device__ int   g_cnt[E];
__device__ int   g_icnt[E];
__device__ float g_colnorm[E];
__device__ float g_sig[E];
__device__ float g_Xp[(size_t)T * C];         // x, tf32-rounded, perm per 8-k group
__device__ float g_W1t[(size_t)E * II * C];   // [e][i][pk]  K-major, tf32, permuted
__device__ float g_W2t[(size_t)E * C * II];   // [e][c][pk]  K-major, tf32, permuted

// permuted column within each 8-k group: kk -> ((kk&3)<<1)|(kk>>2)
#define PCOL(k) (((k) & ~7) | ((((k) & 3) << 1) | (((k) >> 2) & 1)))

// ---------------- helpers ----------------
__device__ __forceinline__ float to_tf32(float f) {
    uint32_t u;
    asm("cvt.rna.tf32.f32 %0, %1;" : "=r"(u) : "f"(f));
    return __uint_as_float(u);
}
__device__ __forceinline__ uint32_t smem_u32(const void* p) {
    uint32_t a;
    asm("{ .reg .u64 t; cvta.to.shared.u64 t, %1; cvt.u32.u64 %0, t; }" : "=r"(a) : "l"(p));
    return a;
}
__device__ __forceinline__ void cpa16(uint32_t dst, const void* src, bool valid) {
    int sz = valid ? 16 : 0;
    asm volatile("cp.async.cg.shared.global [%0], [%1], 16, %2;"
                 :: "r"(dst), "l"(src), "r"(sz) : "memory");
}
#define CP_COMMIT() asm volatile("cp.async.commit_group;" ::: "memory")
#define CP_WAIT(n)  asm volatile("cp.async.wait_group %0;" :: "n"(n) : "memory")

__device__ __forceinline__ void mma16n8k8(float* d, const uint32_t* a, const uint32_t* b) {
    asm volatile(
        "mma.sync.aligned.m16n8k8.row.col.f32.tf32.tf32.f32 "
        "{%0,%1,%2,%3}, {%4,%5,%6,%7}, {%8,%9}, {%0,%1,%2,%3};"
        : "+f"(d[0]), "+f"(d[1]), "+f"(d[2]), "+f"(d[3])
        : "r"(a[0]), "r"(a[1]), "r"(a[2]), "r"(a[3]), "r"(b[0]), "r"(b[1]));
}

__device__ __forceinline__ float gelu_exact(float v) {
    return 0.5f * v * (1.0f + erff(v * 0.70710678118654752f));
}

// ---------------- kernel 0: prep ----------------
__global__ void prep_kernel(const float* __restrict__ sim, const float* __restrict__ gates) {
    int w = threadIdx.x >> 5;
    int lane = threadIdx.x & 31;
    float s = 0.f;
    for (int c = lane; c < C; c += 32) {
        float v = sim[c * E + w];
        s = fmaf(v, v, s);
    }
    #pragma unroll
    for (int o = 16; o; o >>= 1) s += __shfl_xor_sync(FULLMASK, s, o);
    if (lane == 0) {
        g_colnorm[w] = fmaxf(sqrtf(s), 1e-12f);
        g_sig[w]     = 1.f / (1.f + expf(-gates[w]));
        g_cnt[w]     = 0;
        g_icnt[w]    = 0;
    }
}

// ---------------- X pre-round (tf32 + permuted layout) ----------------
__global__ __launch_bounds__(128) void round_x(const float* __restrict__ x) {
    int t = blockIdx.x;
    int c = threadIdx.x * 4;
    float4 v = ((const float4*)(x + (size_t)t * C))[threadIdx.x];
    float* dst = g_Xp + (size_t)t * C;
    dst[PCOL(c)]     = to_tf32(v.x);
    dst[PCOL(c + 1)] = to_tf32(v.y);
    dst[PCOL(c + 2)] = to_tf32(v.z);
    dst[PCOL(c + 3)] = to_tf32(v.w);
}

// ---------------- weight transposes (K-major + tf32 + fragment permutation) -------
__global__ __launch_bounds__(256) void transpose_w1(const float* __restrict__ W1) {
    __shared__ float t[32][33];
    int e = blockIdx.z, c0 = blockIdx.x * 32, i0 = blockIdx.y * 32;
    int tx = threadIdx.x & 31, ty = threadIdx.x >> 5;
    #pragma unroll
    for (int j = 0; j < 32; j += 8)
        t[ty + j][tx] = W1[((size_t)e * C + c0 + ty + j) * II + i0 + tx];
    __syncthreads();
    #pragma unroll
    for (int j = 0; j < 32; j += 8)
        g_W1t[((size_t)e * II + i0 + ty + j) * C + PCOL(c0 + tx)] = to_tf32(t[tx][ty + j]);
}
__global__ __launch_bounds__(256) void transpose_w2(const float* __restrict__ W2) {
    __shared__ float t[32][33];
    int e = blockIdx.z, i0 = blockIdx.x * 32, c0 = blockIdx.y * 32;
    int tx = threadIdx.x & 31, ty = threadIdx.x >> 5;
    #pragma unroll
    for (int j = 0; j < 32; j += 8)
        t[ty + j][tx] = W2[((size_t)e * II + i0 + ty + j) * C + c0 + tx];
    __syncthreads();
    #pragma unroll
    for (int j = 0; j < 32; j += 8)
        g_W2t[((size_t)e * C + c0 + ty + j) * II + PCOL(i0 + tx)] = to_tf32(t[tx][ty + j]);
}

// ---------------- kernel 1: gating (warp-per-token + dual lists) ----------------
__global__ __launch_bounds__(256) void gating_kernel(
    const float* __restrict__ x, const float* __restrict__ sim,
    float* __restrict__ pre_out, float* __restrict__ mask_out) {
    __shared__ float s_x[8 * C];
    __shared__ unsigned char s_act[8][E];

    int tid = threadIdx.x;
    int w = tid >> 5;
    int lane = tid & 31;
    int t0 = blockIdx.x * 8;
    int t = t0 + w;

    const float* xbase = x + (size_t)t0 * C;
    #pragma unroll
    for (int p = 0; p < 16; p++) s_x[tid + p * 256] = xbase[tid + p * 256];
    __syncthreads();

    const float* xw = s_x + w * C;
    float acc = 0.f, nsq = 0.f;
    #pragma unroll 8
    for (int c = 0; c < C; c++) {
        float xc = xw[c];
        acc = fmaf(xc, __ldg(&sim[c * E + lane]), acc);
        nsq = fmaf(xc, xc, nsq);
    }

    float xnorm = fmaxf(sqrtf(nsq), 1e-12f);
    float logit = acc / (xnorm * g_colnorm[lane]);
    float pre   = logit - g_sig[lane];
    float gated = fmaxf(pre, 0.f);

    unsigned act = __ballot_sync(FULLMASK, gated > 0.f);
    float maskv;
    if (act == 0u) {
        int rank = 0;
        #pragma unroll
        for (int j = 0; j < 32; j++) {
            float lj = __shfl_sync(FULLMASK, logit, j);
            rank += (lj > logit) || (lj == logit && j < lane);
        }
        maskv = (rank < KFB) ? 1.f : 0.f;
    } else {
        maskv = (gated > 0.f) ? 1.f : 0.f;
    }

    float maskedv = (maskv > 0.f) ? gated : NEGC;
    float m = maskedv;
    #pragma unroll
    for (int o = 16; o; o >>= 1) m = fmaxf(m, __shfl_xor_sync(FULLMASK, m, o));
    float p = expf(maskedv - m);
    float ssum = p;
    #pragma unroll
    for (int o = 16; o; o >>= 1) ssum += __shfl_xor_sync(FULLMASK, ssum, o);
    float rw = p / ssum;

    pre_out[t * E + lane]  = pre;
    mask_out[t * E + lane] = maskv;
    g_rw[t * E + lane]     = rw;
    s_act[w][lane] = (maskv > 0.f) ? 1 : 0;
    __syncthreads();

    if (tid < E) {
        int e = tid;
        int cntl = 0;
        #pragma unroll
        for (int s2 = 0; s2 < 8; s2++) cntl += s_act[s2][e];
        if (cntl > 0) {
            int base = atomicAdd(&g_cnt[e], cntl);
            for (int s2 = 0; s2 < 8; s2++)
                if (s_act[s2][e]) g_idx[e * T + base++] = t0 + s2;
        }
        if (cntl < 8) {
            int ibase = atomicAdd(&g_icnt[e], 8 - cntl);
            for (int s2 = 0; s2 < 8; s2++)
                if (!s_act[s2][e]) g_iidx[e * T + ibase++] = t0 + s2;
        }
    }
}

// ---------------- fused expert MLP (cp.async double-buffered) + inactive zeroing ----
#define MS 72
#define ABUF_B (128 * MS * 4)               // 36864
#define OFF_A0 1024
#define OFF_A1 (1024 + ABUF_B)              // 37888
#define OFF_B  (1024 + 2 * ABUF_B)          // 74752 (128 rows; phase1 splits 64/64)
#define EM_SMEM (1024 + 3 * ABUF_B)         // 111616

__global__ __launch_bounds__(256) void expert_mlp(float* __restrict__ feo) {
    int e = blockIdx.y;
    int cnt = g_cnt[e];
    int cntB = (cnt + 127) >> 7;
    int tid = threadIdx.x;

    extern __shared__ char smem[];
    int* toks = (int*)smem;

    if ((int)blockIdx.x >= cntB) {
        // ---------- zero path: inactive rows ----------
        int icnt = g_icnt[e];
        int zi0 = ((int)blockIdx.x - cntB) * 128;
        if (zi0 >= icnt) return;
        int nrows = min(128, icnt - zi0);
        if (tid < nrows) toks[tid] = g_iidx[e * T + zi0 + tid];
        __syncthreads();
        float4 z = make_float4(0.f, 0.f, 0.f, 0.f);
        for (int j = tid; j < nrows * 128; j += 256) {
            int r = j >> 7, q = j & 127;
            ((float4*)&feo[((size_t)toks[r] * E + e) * C])[q] = z;
        }
        return;
    }

    // ---------- compute path ----------
    int m0 = blockIdx.x * 128;
    uint32_t sb = smem_u32(smem);
    int wid = tid >> 5, lane = tid & 31;
    if (tid < 128) toks[tid] = (m0 + tid < cnt) ? g_idx[e * T + m0 + tid] : -1;
    __syncthreads();

    int warpM = wid >> 1, warpN = wid & 1;
    int rbase = warpM * 32;
    int lr = lane >> 2, lc = lane & 3;

    uint32_t aoff[2] = { sb + OFF_A0, sb + OFF_A1 };
    uint32_t boff[2] = { sb + OFF_B, sb + OFF_B + 64 * MS * 4 };

    // async stage of one phase-1 k-chunk (X gather + W1)
    auto stage1 = [&](int kc, int b) {
        #pragma unroll
        for (int p = 0; p < 8; p++) {
            int idx = tid + (p << 8);
            int r = idx >> 4, q = idx & 15;
            int tok = toks[r];
            const float* src = g_Xp + (size_t)(tok < 0 ? 0 : tok) * C + kc * 64 + q * 4;
            cpa16(aoff[b] + r * MS * 4 + q * 16, src, tok >= 0);
        }
        #pragma unroll
        for (int p = 0; p < 4; p++) {
            int idx = tid + (p << 8);
            int i = idx >> 4, q = idx & 15;
            const float* src = g_W1t + ((size_t)e * II + i) * C + kc * 64 + q * 4;
            cpa16(boff[b] + i * MS * 4 + q * 16, src, true);
        }
        CP_COMMIT();
    };

    // ---------- phase 1: H = gelu(Xg @ W1^T), warp tile 32x32 ----------
    {
        int nbase = warpN * 32;
        float d[2][4][4];
        #pragma unroll
        for (int mt = 0; mt < 2; mt++)
            #pragma unroll
            for (int nt = 0; nt < 4; nt++)
                #pragma unroll
                for (int i = 0; i < 4; i++) d[mt][nt][i] = 0.f;

        stage1(0, 0);
        #pragma unroll 1
        for (int kc = 0; kc < 8; kc++) {
            if (kc + 1 < 8) { stage1(kc + 1, (kc + 1) & 1); CP_WAIT(1); }
            else            { CP_WAIT(0); }
            __syncthreads();

            float* Ab = (float*)(smem + OFF_A0 + (kc & 1) * ABUF_B);
            float* Bb = (float*)(smem + OFF_B + (kc & 1) * (64 * MS * 4));

            #pragma unroll
            for (int ks = 0; ks < 8; ks++) {
                int k0 = ks * 8;
                uint32_t afr[2][4], bfr[4][2];
                #pragma unroll
                for (int mt = 0; mt < 2; mt++) {
                    int row = rbase + mt * 16 + lr;
                    float2 pa0 = *(float2*)(Ab + row * MS + k0 + lc * 2);
                    float2 pa1 = *(float2*)(Ab + (row + 8) * MS + k0 + lc * 2);
                    afr[mt][0] = __float_as_uint(pa0.x);
                    afr[mt][1] = __float_as_uint(pa1.x);
                    afr[mt][2] = __float_as_uint(pa0.y);
                    afr[mt][3] = __float_as_uint(pa1.y);
                }
                #pragma unroll
                for (int nt = 0; nt < 4; nt++) {
                    int col = nbase + nt * 8 + lr;
                    float2 pb = *(float2*)(Bb + col * MS + k0 + lc * 2);
                    bfr[nt][0] = __float_as_uint(pb.x);
                    bfr[nt][1] = __float_as_uint(pb.y);
                }
                #pragma unroll
                for (int mt = 0; mt < 2; mt++)
                    #pragma unroll
                    for (int nt = 0; nt < 4; nt++)
                        mma16n8k8(d[mt][nt], afr[mt], bfr[nt]);
            }
            __syncthreads();
        }

        // prefetch W2 chunk 0 into Bs region (overlaps with H epilogue)
        {
            #pragma unroll
            for (int p = 0; p < 8; p++) {
                int idx = tid + (p << 8);
                int n = idx >> 4, q = idx & 15;
                const float* src = g_W2t + ((size_t)e * C + n) * II + q * 4;
                cpa16(sb + OFF_B + n * MS * 4 + q * 16, src, true);
            }
            CP_COMMIT();
        }

        // H epilogue -> As0 in permuted layout
        float* H = (float*)(smem + OFF_A0);
        int pos0 = ((lc & 1) << 2) | (lc >> 1);   // perm(2*lc)
        #pragma unroll
        for (int mt = 0; mt < 2; mt++) {
            int r0 = rbase + mt * 16 + lr;
            #pragma unroll
            for (int nt = 0; nt < 4; nt++) {
                int base = nbase + nt * 8;
                H[r0 * MS + base + pos0]           = to_tf32(gelu_exact(d[mt][nt][0]));
                H[r0 * MS + base + pos0 + 2]       = to_tf32(gelu_exact(d[mt][nt][1]));
                H[(r0 + 8) * MS + base + pos0]     = to_tf32(gelu_exact(d[mt][nt][2]));
                H[(r0 + 8) * MS + base + pos0 + 2] = to_tf32(gelu_exact(d[mt][nt][3]));
            }
        }
    }

    // ---------- phase 2: Y = H @ W2^T over 4 n-chunks, warp tile 32x64 ----------
    float* H = (float*)(smem + OFF_A0);
    uint32_t w2off[2] = { sb + OFF_B, sb + OFF_A1 };
    int nbase2 = warpN * 64;

    auto stage2 = [&](int nc, int b) {
        #pragma unroll
        for (int p = 0; p < 8; p++) {
            int idx = tid + (p << 8);
            int n = idx >> 4, q = idx & 15;
            const float* src = g_W2t + ((size_t)e * C + nc * 128 + n) * II + q * 4;
            cpa16(w2off[b] + n * MS * 4 + q * 16, src, true);
        }
        CP_COMMIT();
    };

    #pragma unroll 1
    for (int nc = 0; nc < 4; nc++) {
        if (nc + 1 < 4) { stage2(nc + 1, (nc + 1) & 1); CP_WAIT(1); }
        else            { CP_WAIT(0); }
        __syncthreads();

        float* Wb = (float*)(smem + (nc & 1 ? OFF_A1 : OFF_B));

        float d2[2][8][4];
        #pragma unroll
        for (int mt = 0; mt < 2; mt++)
            #pragma unroll
            for (int nt = 0; nt < 8; nt++)
                #pragma unroll
                for (int i = 0; i < 4; i++) d2[mt][nt][i] = 0.f;

        #pragma unroll
        for (int ks = 0; ks < 8; ks++) {
            int k0 = ks * 8;
            uint32_t afr[2][4], bfr[8][2];
            #pragma unroll
            for (int mt = 0; mt < 2; mt++) {
                int row = rbase + mt * 16 + lr;
                float2 pa0 = *(float2*)(H + row * MS + k0 + lc * 2);
                float2 pa1 = *(float2*)(H + (row + 8) * MS + k0 + lc * 2);
                afr[mt][0] = __float_as_uint(pa0.x);
                afr[mt][1] = __float_as_uint(pa1.x);
                afr[mt][2] = __float_as_uint(pa0.y);
                afr[mt][3] = __float_as_uint(pa1.y);
            }
            #pragma unroll
            for (int nt = 0; nt < 8; nt++) {
                int col = nbase2 + nt * 8 + lr;
                float2 pb = *(float2*)(Wb + col * MS + k0 + lc * 2);
                bfr[nt][0] = __float_as_uint(pb.x);
                bfr[nt][1] = __float_as_uint(pb.y);
            }
            #pragma unroll
            for (int mt = 0; mt < 2; mt++)
                #pragma unroll
                for (int nt = 0; nt < 8; nt++)
                    mma16n8k8(d2[mt][nt], afr[mt], bfr[nt]);
        }

        #pragma unroll
        for (int mt = 0; mt < 2; mt++) {
            int s0 = rbase + mt * 16 + lr, s1 = s0 + 8;
            int tok0 = toks[s0], tok1 = toks[s1];
            #pragma unroll
            for (int nt = 0; nt < 8; nt++) {
                int col = nc * 128 + nbase2 + nt * 8 + lc * 2;
                if (tok0 >= 0)
                    *(float2*)&feo[((size_t)tok0 * E + e) * C + col] =
                        make_float2(d2[mt][nt][0], d2[mt][nt][1]);
                if (tok1 >= 0)
                    *(float2*)&feo[((size_t)tok1 * E + e) * C + col] =
                        make_float2(d2[mt][nt][2], d2[mt][nt][3]);
            }
        }
        __syncthreads();
    }
}

// ---------------- final reduce: final = sum_e rw * feo (active rows only) ----------
__global__ __launch_bounds__(128) void final_reduce(
    const float* __restrict__ maskp, const float* __restrict__ feo,
    float* __restrict__ final_out) {
    int t = blockIdx.x;
    int tid = threadIdx.x;
    float4 acc = make_float4(0.f, 0.f, 0.f, 0.f);
    #pragma unroll 1
    for (int e = 0; e < E; e++) {
        if (maskp[(size_t)t * E + e] > 0.f) {
            float wv = g_rw[t * E + e];
            float4 v = ((const float4*)&feo[((size_t)t * E + e) * C])[tid];
            acc.x = fmaf(wv, v.x, acc.x);
            acc.y = fmaf(wv, v.y, acc.y);
            acc.z = fmaf(wv, v.z, acc.z);
            acc.w = fmaf(wv, v.w, acc.w);
        }
    }
    ((float4*)&final_out[(size_t)t * C])[tid] = acc;
}

// ---------------- launch ----------------
extern "C" void kernel_launch(void* const* d_in, const int* in_sizes, int n_in,
                              void* d_out, int out_size) {
    const float* x     = (const float*)d_in[0];
    const float* sim   = (const float*)d_in[1];
    const float* gates = (const float*)d_in[2];
    const float* W1    = (const float*)d_in[3];
    const float* W2    = (const float*)d_in[4];

    float* out       = (float*)d_out;
    float* final_out = out;
    float* feo       = out + (size_t)T * C;
    float* pre       = feo + (size_t)T * E * C;
    float* maskp     = pre + (size_t)T * E;

    cudaFuncSetAttribute(expert_mlp, cudaFuncAttributeMaxDynamicSharedMemorySize, EM_SMEM);

    prep_kernel<<<1, 1024>>>(sim, gates);
    transpose_w1<<<dim3(C / 32, II / 32, E), 256>>>(W1);
    transpose_w2<<<dim3(II / 32, C / 32, E), 256>>>(W2);
    round_x<<<T, 128>>>(x);
    gating_kernel<<<T / 8, 256>>>(x, sim, pre, maskp);
    expert_mlp<<<dim3(T / 128 + 1, E), 256, EM_SMEM>>>(feo);
    final_reduce<<<T, 128>>>(maskp, feo, final_out);
}

// round 7
// speedup vs baseline: 1.2670x; 1.0253x over previous
#include <cuda_runtime.h>
#include <cstdint>
#include <math.h>

#define T 8192
#define C 512
#define II 64
#define E 32
#define KFB (E/2)
#define FULLMASK 0xffffffffu
#define NEGC (-3.3895313892515355e+38f)

// ---------------- device scratch ----------------
__device__ float g_rw[T * E];
__device__ int   g_idx[E * T];        // per-expert active token lists
__device__ int   g_iidx[E * T];       // per-expert inactive token lists
__device__ int   g_cnt[E];
__device__ int   g_icnt[E];
__device__ float g_colnorm[E];
__device__ float g_sig[E];
__device__ float g_Xp[(size_t)T * C];         // x, tf32-rounded, perm per 8-k group
__device__ float g_W1t[(size_t)E * II * C];   // [e][i][pk]  K-major, tf32, permuted
__device__ float g_W2t[(size_t)E * C * II];   // [e][c][pk]  K-major, tf32, permuted

// permuted column within each 8-k group: kk -> ((kk&3)<<1)|(kk>>2)
#define PCOL(k) (((k) & ~7) | ((((k) & 3) << 1) | (((k) >> 2) & 1)))

// ---------------- helpers ----------------
__device__ __forceinline__ float to_tf32(float f) {
    uint32_t u;
    asm("cvt.rna.tf32.f32 %0, %1;" : "=r"(u) : "f"(f));
    return __uint_as_float(u);
}
__device__ __forceinline__ uint32_t smem_u32(const void* p) {
    uint32_t a;
    asm("{ .reg .u64 t; cvta.to.shared.u64 t, %1; cvt.u32.u64 %0, t; }" : "=r"(a) : "l"(p));
    return a;
}
__device__ __forceinline__ void cpa16(uint32_t dst, const void* src, bool valid) {
    int sz = valid ? 16 : 0;
    asm volatile("cp.async.cg.shared.global [%0], [%1], 16, %2;"
                 :: "r"(dst), "l"(src), "r"(sz) : "memory");
}
#define CP_COMMIT() asm volatile("cp.async.commit_group;" ::: "memory")
#define CP_WAIT(n)  asm volatile("cp.async.wait_group %0;" :: "n"(n) : "memory")

__device__ __forceinline__ void mma16n8k8(float* d, const uint32_t* a, const uint32_t* b) {
    asm volatile(
        "mma.sync.aligned.m16n8k8.row.col.f32.tf32.tf32.f32 "
        "{%0,%1,%2,%3}, {%4,%5,%6,%7}, {%8,%9}, {%0,%1,%2,%3};"
        : "+f"(d[0]), "+f"(d[1]), "+f"(d[2]), "+f"(d[3])
        : "r"(a[0]), "r"(a[1]), "r"(a[2]), "r"(a[3]), "r"(b[0]), "r"(b[1]));
}

__device__ __forceinline__ float gelu_exact(float v) {
    return 0.5f * v * (1.0f + erff(v * 0.70710678118654752f));
}

// ---------------- kernel 0: prep ----------------
__global__ void prep_kernel(const float* __restrict__ sim, const float* __restrict__ gates) {
    int w = threadIdx.x >> 5;
    int lane = threadIdx.x & 31;
    float s = 0.f;
    for (int c = lane; c < C; c += 32) {
        float v = sim[c * E + w];
        s = fmaf(v, v, s);
    }
    #pragma unroll
    for (int o = 16; o; o >>= 1) s += __shfl_xor_sync(FULLMASK, s, o);
    if (lane == 0) {
        g_colnorm[w] = fmaxf(sqrtf(s), 1e-12f);
        g_sig[w]     = 1.f / (1.f + expf(-gates[w]));
        g_cnt[w]     = 0;
        g_icnt[w]    = 0;
    }
}

// ---------------- weight transposes (K-major + tf32 + fragment permutation) -------
__global__ __launch_bounds__(256) void transpose_w1(const float* __restrict__ W1) {
    __shared__ float t[32][33];
    int e = blockIdx.z, c0 = blockIdx.x * 32, i0 = blockIdx.y * 32;
    int tx = threadIdx.x & 31, ty = threadIdx.x >> 5;
    #pragma unroll
    for (int j = 0; j < 32; j += 8)
        t[ty + j][tx] = W1[((size_t)e * C + c0 + ty + j) * II + i0 + tx];
    __syncthreads();
    #pragma unroll
    for (int j = 0; j < 32; j += 8)
        g_W1t[((size_t)e * II + i0 + ty + j) * C + PCOL(c0 + tx)] = to_tf32(t[tx][ty + j]);
}
__global__ __launch_bounds__(256) void transpose_w2(const float* __restrict__ W2) {
    __shared__ float t[32][33];
    int e = blockIdx.z, i0 = blockIdx.x * 32, c0 = blockIdx.y * 32;
    int tx = threadIdx.x & 31, ty = threadIdx.x >> 5;
    #pragma unroll
    for (int j = 0; j < 32; j += 8)
        t[ty + j][tx] = W2[((size_t)e * II + i0 + ty + j) * C + c0 + tx];
    __syncthreads();
    #pragma unroll
    for (int j = 0; j < 32; j += 8)
        g_W2t[((size_t)e * C + c0 + ty + j) * II + PCOL(i0 + tx)] = to_tf32(t[tx][ty + j]);
}

// ---------------- kernel 1: gating (warp-per-token + dual lists + X pre-round) -----
__global__ __launch_bounds__(256) void gating_kernel(
    const float* __restrict__ x, const float* __restrict__ sim,
    float* __restrict__ pre_out, float* __restrict__ mask_out) {
    __shared__ float s_x[8 * C];
    __shared__ unsigned char s_act[8][E];

    int tid = threadIdx.x;
    int w = tid >> 5;
    int lane = tid & 31;
    int t0 = blockIdx.x * 8;
    int t = t0 + w;

    const float* xbase = x + (size_t)t0 * C;
    #pragma unroll
    for (int p = 0; p < 16; p++) s_x[tid + p * 256] = xbase[tid + p * 256];
    __syncthreads();

    // fused round_x: emit tf32-rounded, fragment-permuted X
    #pragma unroll
    for (int p = 0; p < 16; p++) {
        int idx = tid + p * 256;          // = r*512 + c
        int r = idx >> 9, c = idx & 511;
        g_Xp[(size_t)(t0 + r) * C + PCOL(c)] = to_tf32(s_x[idx]);
    }

    const float* xw = s_x + w * C;
    float acc = 0.f, nsq = 0.f;
    #pragma unroll 8
    for (int c = 0; c < C; c++) {
        float xc = xw[c];
        acc = fmaf(xc, __ldg(&sim[c * E + lane]), acc);
        nsq = fmaf(xc, xc, nsq);
    }

    float xnorm = fmaxf(sqrtf(nsq), 1e-12f);
    float logit = acc / (xnorm * g_colnorm[lane]);
    float pre   = logit - g_sig[lane];
    float gated = fmaxf(pre, 0.f);

    unsigned act = __ballot_sync(FULLMASK, gated > 0.f);
    float maskv;
    if (act == 0u) {
        int rank = 0;
        #pragma unroll
        for (int j = 0; j < 32; j++) {
            float lj = __shfl_sync(FULLMASK, logit, j);
            rank += (lj > logit) || (lj == logit && j < lane);
        }
        maskv = (rank < KFB) ? 1.f : 0.f;
    } else {
        maskv = (gated > 0.f) ? 1.f : 0.f;
    }

    float maskedv = (maskv > 0.f) ? gated : NEGC;
    float m = maskedv;
    #pragma unroll
    for (int o = 16; o; o >>= 1) m = fmaxf(m, __shfl_xor_sync(FULLMASK, m, o));
    float p = expf(maskedv - m);
    float ssum = p;
    #pragma unroll
    for (int o = 16; o; o >>= 1) ssum += __shfl_xor_sync(FULLMASK, ssum, o);
    float rw = p / ssum;

    pre_out[t * E + lane]  = pre;
    mask_out[t * E + lane] = maskv;
    g_rw[t * E + lane]     = rw;
    s_act[w][lane] = (maskv > 0.f) ? 1 : 0;
    __syncthreads();

    if (tid < E) {
        int e = tid;
        int cntl = 0;
        #pragma unroll
        for (int s2 = 0; s2 < 8; s2++) cntl += s_act[s2][e];
        if (cntl > 0) {
            int base = atomicAdd(&g_cnt[e], cntl);
            for (int s2 = 0; s2 < 8; s2++)
                if (s_act[s2][e]) g_idx[e * T + base++] = t0 + s2;
        }
        if (cntl < 8) {
            int ibase = atomicAdd(&g_icnt[e], 8 - cntl);
            for (int s2 = 0; s2 < 8; s2++)
                if (!s_act[s2][e]) g_iidx[e * T + ibase++] = t0 + s2;
        }
    }
}

// ---------------- fused expert MLP (cp.async double-buffered) + inactive zeroing ----
#define MS 72
#define ABUF_B (128 * MS * 4)               // 36864
#define OFF_A0 1024
#define OFF_A1 (1024 + ABUF_B)              // 37888
#define OFF_B  (1024 + 2 * ABUF_B)          // 74752 (128 rows; phase1 splits 64/64)
#define EM_SMEM (1024 + 3 * ABUF_B)         // 111616

__global__ __launch_bounds__(256, 2) void expert_mlp(float* __restrict__ feo) {
    int e = blockIdx.y;
    int cnt = g_cnt[e];
    int cntB = (cnt + 127) >> 7;
    int tid = threadIdx.x;

    extern __shared__ char smem[];
    int* toks = (int*)smem;

    if ((int)blockIdx.x >= cntB) {
        // ---------- zero path: inactive rows ----------
        int icnt = g_icnt[e];
        int zi0 = ((int)blockIdx.x - cntB) * 128;
        if (zi0 >= icnt) return;
        int nrows = min(128, icnt - zi0);
        if (tid < nrows) toks[tid] = g_iidx[e * T + zi0 + tid];
        __syncthreads();
        float4 z = make_float4(0.f, 0.f, 0.f, 0.f);
        for (int j = tid; j < nrows * 128; j += 256) {
            int r = j >> 7, q = j & 127;
            ((float4*)&feo[((size_t)toks[r] * E + e) * C])[q] = z;
        }
        return;
    }

    // ---------- compute path ----------
    int m0 = blockIdx.x * 128;
    uint32_t sb = smem_u32(smem);
    int wid = tid >> 5, lane = tid & 31;
    if (tid < 128) toks[tid] = (m0 + tid < cnt) ? g_idx[e * T + m0 + tid] : -1;
    __syncthreads();

    int warpM = wid >> 1, warpN = wid & 1;
    int rbase = warpM * 32;
    int lr = lane >> 2, lc = lane & 3;

    uint32_t aoff[2] = { sb + OFF_A0, sb + OFF_A1 };
    uint32_t boff[2] = { sb + OFF_B, sb + OFF_B + 64 * MS * 4 };

    auto stage1 = [&](int kc, int b) {
        #pragma unroll
        for (int p = 0; p < 8; p++) {
            int idx = tid + (p << 8);
            int r = idx >> 4, q = idx & 15;
            int tok = toks[r];
            const float* src = g_Xp + (size_t)(tok < 0 ? 0 : tok) * C + kc * 64 + q * 4;
            cpa16(aoff[b] + r * MS * 4 + q * 16, src, tok >= 0);
        }
        #pragma unroll
        for (int p = 0; p < 4; p++) {
            int idx = tid + (p << 8);
            int i = idx >> 4, q = idx & 15;
            const float* src = g_W1t + ((size_t)e * II + i) * C + kc * 64 + q * 4;
            cpa16(boff[b] + i * MS * 4 + q * 16, src, true);
        }
        CP_COMMIT();
    };

    // ---------- phase 1: H = gelu(Xg @ W1^T), warp tile 32x32 ----------
    {
        int nbase = warpN * 32;
        float d[2][4][4];
        #pragma unroll
        for (int mt = 0; mt < 2; mt++)
            #pragma unroll
            for (int nt = 0; nt < 4; nt++)
                #pragma unroll
                for (int i = 0; i < 4; i++) d[mt][nt][i] = 0.f;

        stage1(0, 0);
        #pragma unroll 1
        for (int kc = 0; kc < 8; kc++) {
            if (kc + 1 < 8) { stage1(kc + 1, (kc + 1) & 1); CP_WAIT(1); }
            else            { CP_WAIT(0); }
            __syncthreads();

            float* Ab = (float*)(smem + OFF_A0 + (kc & 1) * ABUF_B);
            float* Bb = (float*)(smem + OFF_B + (kc & 1) * (64 * MS * 4));

            #pragma unroll
            for (int ks = 0; ks < 8; ks++) {
                int k0 = ks * 8;
                uint32_t afr[2][4], bfr[4][2];
                #pragma unroll
                for (int mt = 0; mt < 2; mt++) {
                    int row = rbase + mt * 16 + lr;
                    float2 pa0 = *(float2*)(Ab + row * MS + k0 + lc * 2);
                    float2 pa1 = *(float2*)(Ab + (row + 8) * MS + k0 + lc * 2);
                    afr[mt][0] = __float_as_uint(pa0.x);
                    afr[mt][1] = __float_as_uint(pa1.x);
                    afr[mt][2] = __float_as_uint(pa0.y);
                    afr[mt][3] = __float_as_uint(pa1.y);
                }
                #pragma unroll
                for (int nt = 0; nt < 4; nt++) {
                    int col = nbase + nt * 8 + lr;
                    float2 pb = *(float2*)(Bb + col * MS + k0 + lc * 2);
                    bfr[nt][0] = __float_as_uint(pb.x);
                    bfr[nt][1] = __float_as_uint(pb.y);
                }
                #pragma unroll
                for (int mt = 0; mt < 2; mt++)
                    #pragma unroll
                    for (int nt = 0; nt < 4; nt++)
                        mma16n8k8(d[mt][nt], afr[mt], bfr[nt]);
            }
            __syncthreads();
        }

        // prefetch W2 chunk 0 (overlaps with H epilogue)
        {
            #pragma unroll
            for (int p = 0; p < 8; p++) {
                int idx = tid + (p << 8);
                int n = idx >> 4, q = idx & 15;
                const float* src = g_W2t + ((size_t)e * C + n) * II + q * 4;
                cpa16(sb + OFF_B + n * MS * 4 + q * 16, src, true);
            }
            CP_COMMIT();
        }

        // H epilogue -> As0 in permuted layout
        float* H = (float*)(smem + OFF_A0);
        int pos0 = ((lc & 1) << 2) | (lc >> 1);   // perm(2*lc)
        #pragma unroll
        for (int mt = 0; mt < 2; mt++) {
            int r0 = rbase + mt * 16 + lr;
            #pragma unroll
            for (int nt = 0; nt < 4; nt++) {
                int base = nbase + nt * 8;
                H[r0 * MS + base + pos0]           = to_tf32(gelu_exact(d[mt][nt][0]));
                H[r0 * MS + base + pos0 + 2]       = to_tf32(gelu_exact(d[mt][nt][1]));
                H[(r0 + 8) * MS + base + pos0]     = to_tf32(gelu_exact(d[mt][nt][2]));
                H[(r0 + 8) * MS + base + pos0 + 2] = to_tf32(gelu_exact(d[mt][nt][3]));
            }
        }
    }

    // ---------- phase 2: Y = H @ W2^T over 4 n-chunks, warp tile 32x64 ----------
    float* H = (float*)(smem + OFF_A0);
    uint32_t w2off[2] = { sb + OFF_B, sb + OFF_A1 };
    int nbase2 = warpN * 64;

    auto stage2 = [&](int nc, int b) {
        #pragma unroll
        for (int p = 0; p < 8; p++) {
            int idx = tid + (p << 8);
            int n = idx >> 4, q = idx & 15;
            const float* src = g_W2t + ((size_t)e * C + nc * 128 + n) * II + q * 4;
            cpa16(w2off[b] + n * MS * 4 + q * 16, src, true);
        }
        CP_COMMIT();
    };

    #pragma unroll 1
    for (int nc = 0; nc < 4; nc++) {
        if (nc + 1 < 4) { stage2(nc + 1, (nc + 1) & 1); CP_WAIT(1); }
        else            { CP_WAIT(0); }
        __syncthreads();

        float* Wb = (float*)(smem + (nc & 1 ? OFF_A1 : OFF_B));

        float d2[2][8][4];
        #pragma unroll
        for (int mt = 0; mt < 2; mt++)
            #pragma unroll
            for (int nt = 0; nt < 8; nt++)
                #pragma unroll
                for (int i = 0; i < 4; i++) d2[mt][nt][i] = 0.f;

        #pragma unroll
        for (int ks = 0; ks < 8; ks++) {
            int k0 = ks * 8;
            uint32_t afr[2][4], bfr[8][2];
            #pragma unroll
            for (int mt = 0; mt < 2; mt++) {
                int row = rbase + mt * 16 + lr;
                float2 pa0 = *(float2*)(H + row * MS + k0 + lc * 2);
                float2 pa1 = *(float2*)(H + (row + 8) * MS + k0 + lc * 2);
                afr[mt][0] = __float_as_uint(pa0.x);
                afr[mt][1] = __float_as_uint(pa1.x);
                afr[mt][2] = __float_as_uint(pa0.y);
                afr[mt][3] = __float_as_uint(pa1.y);
            }
            #pragma unroll
            for (int nt = 0; nt < 8; nt++) {
                int col = nbase2 + nt * 8 + lr;
                float2 pb = *(float2*)(Wb + col * MS + k0 + lc * 2);
                bfr[nt][0] = __float_as_uint(pb.x);
                bfr[nt][1] = __float_as_uint(pb.y);
            }
            #pragma unroll
            for (int mt = 0; mt < 2; mt++)
                #pragma unroll
                for (int nt = 0; nt < 8; nt++)
                    mma16n8k8(d2[mt][nt], afr[mt], bfr[nt]);
        }

        #pragma unroll
        for (int mt = 0; mt < 2; mt++) {
            int s0 = rbase + mt * 16 + lr, s1 = s0 + 8;
            int tok0 = toks[s0], tok1 = toks[s1];
            #pragma unroll
            for (int nt = 0; nt < 8; nt++) {
                int col = nc * 128 + nbase2 + nt * 8 + lc * 2;
                if (tok0 >= 0)
                    *(float2*)&feo[((size_t)tok0 * E + e) * C + col] =
                        make_float2(d2[mt][nt][0], d2[mt][nt][1]);
                if (tok1 >= 0)
                    *(float2*)&feo[((size_t)tok1 * E + e) * C + col] =
                        make_float2(d2[mt][nt][2], d2[mt][nt][3]);
            }
        }
        __syncthreads();
    }
}

// ---------------- final reduce: compact active list + 4 independent chains ---------
__global__ __launch_bounds__(128) void final_reduce(
    const float* __restrict__ maskp, const float* __restrict__ feo,
    float* __restrict__ final_out) {
    int t = blockIdx.x;
    int tid = threadIdx.x;
    int lane = tid & 31;
    __shared__ float s_w[E];
    __shared__ int   s_ei[E];
    __shared__ int   s_na;

    if (tid < 32) {
        float mv = maskp[(size_t)t * E + lane];
        unsigned act = __ballot_sync(FULLMASK, mv > 0.f);
        int rank = __popc(act & ((1u << lane) - 1u));
        if (mv > 0.f) {
            s_ei[rank] = lane;
            s_w[rank]  = g_rw[t * E + lane];
        }
        if (lane == 0) s_na = __popc(act);
    }
    __syncthreads();

    int na = s_na;
    const float4* base = (const float4*)&feo[(size_t)t * E * C];
    float4 a0 = make_float4(0.f, 0.f, 0.f, 0.f), a1 = a0, a2 = a0, a3 = a0;
    int i = 0;
    for (; i + 4 <= na; i += 4) {
        float w0 = s_w[i], w1 = s_w[i + 1], w2 = s_w[i + 2], w3 = s_w[i + 3];
        float4 v0 = base[s_ei[i]     * 128 + tid];
        float4 v1 = base[s_ei[i + 1] * 128 + tid];
        float4 v2 = base[s_ei[i + 2] * 128 + tid];
        float4 v3 = base[s_ei[i + 3] * 128 + tid];
        a0.x = fmaf(w0, v0.x, a0.x); a0.y = fmaf(w0, v0.y, a0.y);
        a0.z = fmaf(w0, v0.z, a0.z); a0.w = fmaf(w0, v0.w, a0.w);
        a1.x = fmaf(w1, v1.x, a1.x); a1.y = fmaf(w1, v1.y, a1.y);
        a1.z = fmaf(w1, v1.z, a1.z); a1.w = fmaf(w1, v1.w, a1.w);
        a2.x = fmaf(w2, v2.x, a2.x); a2.y = fmaf(w2, v2.y, a2.y);
        a2.z = fmaf(w2, v2.z, a2.z); a2.w = fmaf(w2, v2.w, a2.w);
        a3.x = fmaf(w3, v3.x, a3.x); a3.y = fmaf(w3, v3.y, a3.y);
        a3.z = fmaf(w3, v3.z, a3.z); a3.w = fmaf(w3, v3.w, a3.w);
    }
    for (; i < na; i++) {
        float w0 = s_w[i];
        float4 v0 = base[s_ei[i] * 128 + tid];
        a0.x = fmaf(w0, v0.x, a0.x); a0.y = fmaf(w0, v0.y, a0.y);
        a0.z = fmaf(w0, v0.z, a0.z); a0.w = fmaf(w0, v0.w, a0.w);
    }
    float4 acc;
    acc.x = (a0.x + a1.x) + (a2.x + a3.x);
    acc.y = (a0.y + a1.y) + (a2.y + a3.y);
    acc.z = (a0.z + a1.z) + (a2.z + a3.z);
    acc.w = (a0.w + a1.w) + (a2.w + a3.w);
    ((float4*)&final_out[(size_t)t * C])[tid] = acc;
}

// ---------------- launch ----------------
extern "C" void kernel_launch(void* const* d_in, const int* in_sizes, int n_in,
                              void* d_out, int out_size) {
    const float* x     = (const float*)d_in[0];
    const float* sim   = (const float*)d_in[1];
    const float* gates = (const float*)d_in[2];
    const float* W1    = (const float*)d_in[3];
    const float* W2    = (const float*)d_in[4];

    float* out       = (float*)d_out;
    float* final_out = out;
    float* feo       = out + (size_t)T * C;
    float* pre       = feo + (size_t)T * E * C;
    float* maskp     = pre + (size_t)T * E;

    cudaFuncSetAttribute(expert_mlp, cudaFuncAttributeMaxDynamicSharedMemorySize, EM_SMEM);

    prep_kernel<<<1, 1024>>>(sim, gates);
    transpose_w1<<<dim3(C / 32, II / 32, E), 256>>>(W1);
    transpose_w2<<<dim3(II / 32, C / 32, E), 256>>>(W2);
    gating_kernel<<<T / 8, 256>>>(x, sim, pre, maskp);
    expert_mlp<<<dim3(T / 128 + 1, E), 256, EM_SMEM>>>(feo);
    final_reduce<<<T, 128>>>(maskp, feo, final_out);
}

// round 8
// speedup vs baseline: 1.2697x; 1.0022x over previous
#include <cuda_runtime.h>
#include <cstdint>
#include <math.h>

#define T 8192
#define C 512
#define II 64
#define E 32
#define KFB (E/2)
#define FULLMASK 0xffffffffu
#define NEGC (-3.3895313892515355e+38f)

// ---------------- device scratch ----------------
__device__ float g_rw[T * E];
__device__ int   g_idx[E * T];        // per-expert active token lists
__device__ int   g_iidx[E * T];       // per-expert inactive token lists
__device__ int   g_cnt[E];
__device__ int   g_icnt[E];
__device__ float g_colnorm[E];
__device__ float g_sig[E];
__device__ float g_Xp[(size_t)T * C];         // x, tf32-rounded, perm per 8-k group
__device__ float g_W1t[(size_t)E * II * C];   // [e][i][pk]  K-major, tf32, permuted
__device__ float g_W2t[(size_t)E * C * II];   // [e][c][pk]  K-major, tf32, permuted

// permuted column within each 8-k group: kk -> ((kk&3)<<1)|(kk>>2)
#define PCOL(k) (((k) & ~7) | ((((k) & 3) << 1) | (((k) >> 2) & 1)))

// ---------------- helpers ----------------
__device__ __forceinline__ float to_tf32(float f) {
    uint32_t u;
    asm("cvt.rna.tf32.f32 %0, %1;" : "=r"(u) : "f"(f));
    return __uint_as_float(u);
}
__device__ __forceinline__ uint32_t smem_u32(const void* p) {
    uint32_t a;
    asm("{ .reg .u64 t; cvta.to.shared.u64 t, %1; cvt.u32.u64 %0, t; }" : "=r"(a) : "l"(p));
    return a;
}
__device__ __forceinline__ void cpa16(uint32_t dst, const void* src, bool valid) {
    int sz = valid ? 16 : 0;
    asm volatile("cp.async.cg.shared.global [%0], [%1], 16, %2;"
                 :: "r"(dst), "l"(src), "r"(sz) : "memory");
}
#define CP_COMMIT() asm volatile("cp.async.commit_group;" ::: "memory")
#define CP_WAIT(n)  asm volatile("cp.async.wait_group %0;" :: "n"(n) : "memory")

__device__ __forceinline__ void mma16n8k8(float* d, const uint32_t* a, const uint32_t* b) {
    asm volatile(
        "mma.sync.aligned.m16n8k8.row.col.f32.tf32.tf32.f32 "
        "{%0,%1,%2,%3}, {%4,%5,%6,%7}, {%8,%9}, {%0,%1,%2,%3};"
        : "+f"(d[0]), "+f"(d[1]), "+f"(d[2]), "+f"(d[3])
        : "r"(a[0]), "r"(a[1]), "r"(a[2]), "r"(a[3]), "r"(b[0]), "r"(b[1]));
}

__device__ __forceinline__ float gelu_exact(float v) {
    return 0.5f * v * (1.0f + erff(v * 0.70710678118654752f));
}

// ---------------- kernel 0: prep ----------------
__global__ void prep_kernel(const float* __restrict__ sim, const float* __restrict__ gates) {
    int w = threadIdx.x >> 5;
    int lane = threadIdx.x & 31;
    float s = 0.f;
    for (int c = lane; c < C; c += 32) {
        float v = sim[c * E + w];
        s = fmaf(v, v, s);
    }
    #pragma unroll
    for (int o = 16; o; o >>= 1) s += __shfl_xor_sync(FULLMASK, s, o);
    if (lane == 0) {
        g_colnorm[w] = fmaxf(sqrtf(s), 1e-12f);
        g_sig[w]     = 1.f / (1.f + expf(-gates[w]));
        g_cnt[w]     = 0;
        g_icnt[w]    = 0;
    }
}

// ---------------- X pre-round (tf32 + permuted layout), standalone ----------------
__global__ __launch_bounds__(128) void round_x(const float* __restrict__ x) {
    int t = blockIdx.x;
    int c = threadIdx.x * 4;
    float4 v = ((const float4*)(x + (size_t)t * C))[threadIdx.x];
    float* dst = g_Xp + (size_t)t * C;
    dst[PCOL(c)]     = to_tf32(v.x);
    dst[PCOL(c + 1)] = to_tf32(v.y);
    dst[PCOL(c + 2)] = to_tf32(v.z);
    dst[PCOL(c + 3)] = to_tf32(v.w);
}

// ---------------- weight transposes (K-major + tf32 + fragment permutation) -------
__global__ __launch_bounds__(256) void transpose_w1(const float* __restrict__ W1) {
    __shared__ float t[32][33];
    int e = blockIdx.z, c0 = blockIdx.x * 32, i0 = blockIdx.y * 32;
    int tx = threadIdx.x & 31, ty = threadIdx.x >> 5;
    #pragma unroll
    for (int j = 0; j < 32; j += 8)
        t[ty + j][tx] = W1[((size_t)e * C + c0 + ty + j) * II + i0 + tx];
    __syncthreads();
    #pragma unroll
    for (int j = 0; j < 32; j += 8)
        g_W1t[((size_t)e * II + i0 + ty + j) * C + PCOL(c0 + tx)] = to_tf32(t[tx][ty + j]);
}
__global__ __launch_bounds__(256) void transpose_w2(const float* __restrict__ W2) {
    __shared__ float t[32][33];
    int e = blockIdx.z, i0 = blockIdx.x * 32, c0 = blockIdx.y * 32;
    int tx = threadIdx.x & 31, ty = threadIdx.x >> 5;
    #pragma unroll
    for (int j = 0; j < 32; j += 8)
        t[ty + j][tx] = W2[((size_t)e * II + i0 + ty + j) * C + c0 + tx];
    __syncthreads();
    #pragma unroll
    for (int j = 0; j < 32; j += 8)
        g_W2t[((size_t)e * C + c0 + ty + j) * II + PCOL(i0 + tx)] = to_tf32(t[tx][ty + j]);
}

// ---------------- kernel 1: gating (warp-per-token + dual lists) ----------------
__global__ __launch_bounds__(256) void gating_kernel(
    const float* __restrict__ x, const float* __restrict__ sim,
    float* __restrict__ pre_out, float* __restrict__ mask_out) {
    __shared__ float s_x[8 * C];
    __shared__ unsigned char s_act[8][E];

    int tid = threadIdx.x;
    int w = tid >> 5;
    int lane = tid & 31;
    int t0 = blockIdx.x * 8;
    int t = t0 + w;

    const float* xbase = x + (size_t)t0 * C;
    #pragma unroll
    for (int p = 0; p < 16; p++) s_x[tid + p * 256] = xbase[tid + p * 256];
    __syncthreads();

    const float* xw = s_x + w * C;
    float acc = 0.f, nsq = 0.f;
    #pragma unroll 8
    for (int c = 0; c < C; c++) {
        float xc = xw[c];
        acc = fmaf(xc, __ldg(&sim[c * E + lane]), acc);
        nsq = fmaf(xc, xc, nsq);
    }

    float xnorm = fmaxf(sqrtf(nsq), 1e-12f);
    float logit = acc / (xnorm * g_colnorm[lane]);
    float pre   = logit - g_sig[lane];
    float gated = fmaxf(pre, 0.f);

    unsigned act = __ballot_sync(FULLMASK, gated > 0.f);
    float maskv;
    if (act == 0u) {
        int rank = 0;
        #pragma unroll
        for (int j = 0; j < 32; j++) {
            float lj = __shfl_sync(FULLMASK, logit, j);
            rank += (lj > logit) || (lj == logit && j < lane);
        }
        maskv = (rank < KFB) ? 1.f : 0.f;
    } else {
        maskv = (gated > 0.f) ? 1.f : 0.f;
    }

    float maskedv = (maskv > 0.f) ? gated : NEGC;
    float m = maskedv;
    #pragma unroll
    for (int o = 16; o; o >>= 1) m = fmaxf(m, __shfl_xor_sync(FULLMASK, m, o));
    float p = expf(maskedv - m);
    float ssum = p;
    #pragma unroll
    for (int o = 16; o; o >>= 1) ssum += __shfl_xor_sync(FULLMASK, ssum, o);
    float rw = p / ssum;

    pre_out[t * E + lane]  = pre;
    mask_out[t * E + lane] = maskv;
    g_rw[t * E + lane]     = rw;
    s_act[w][lane] = (maskv > 0.f) ? 1 : 0;
    __syncthreads();

    if (tid < E) {
        int e = tid;
        int cntl = 0;
        #pragma unroll
        for (int s2 = 0; s2 < 8; s2++) cntl += s_act[s2][e];
        if (cntl > 0) {
            int base = atomicAdd(&g_cnt[e], cntl);
            for (int s2 = 0; s2 < 8; s2++)
                if (s_act[s2][e]) g_idx[e * T + base++] = t0 + s2;
        }
        if (cntl < 8) {
            int ibase = atomicAdd(&g_icnt[e], 8 - cntl);
            for (int s2 = 0; s2 < 8; s2++)
                if (!s_act[s2][e]) g_iidx[e * T + ibase++] = t0 + s2;
        }
    }
}

// ---------------- fused expert MLP (cp.async double-buffered) + inactive zeroing ----
#define MS 72
#define ABUF_B (128 * MS * 4)               // 36864
#define OFF_A0 1024
#define OFF_A1 (1024 + ABUF_B)              // 37888
#define OFF_B  (1024 + 2 * ABUF_B)          // 74752 (128 rows; phase1 splits 64/64)
#define EM_SMEM (1024 + 3 * ABUF_B)         // 111616

__global__ __launch_bounds__(256, 2) void expert_mlp(float* __restrict__ feo) {
    int e = blockIdx.y;
    int cnt = g_cnt[e];
    int cntB = (cnt + 127) >> 7;
    int tid = threadIdx.x;

    extern __shared__ char smem[];
    int* toks = (int*)smem;

    if ((int)blockIdx.x >= cntB) {
        // ---------- zero path: inactive rows ----------
        int icnt = g_icnt[e];
        int zi0 = ((int)blockIdx.x - cntB) * 128;
        if (zi0 >= icnt) return;
        int nrows = min(128, icnt - zi0);
        if (tid < nrows) toks[tid] = g_iidx[e * T + zi0 + tid];
        __syncthreads();
        float4 z = make_float4(0.f, 0.f, 0.f, 0.f);
        for (int j = tid; j < nrows * 128; j += 256) {
            int r = j >> 7, q = j & 127;
            ((float4*)&feo[((size_t)toks[r] * E + e) * C])[q] = z;
        }
        return;
    }

    // ---------- compute path ----------
    int m0 = blockIdx.x * 128;
    uint32_t sb = smem_u32(smem);
    int wid = tid >> 5, lane = tid & 31;
    if (tid < 128) toks[tid] = (m0 + tid < cnt) ? g_idx[e * T + m0 + tid] : -1;
    __syncthreads();

    int warpM = wid >> 1, warpN = wid & 1;
    int rbase = warpM * 32;
    int lr = lane >> 2, lc = lane & 3;

    uint32_t aoff[2] = { sb + OFF_A0, sb + OFF_A1 };
    uint32_t boff[2] = { sb + OFF_B, sb + OFF_B + 64 * MS * 4 };

    auto stage1 = [&](int kc, int b) {
        #pragma unroll
        for (int p = 0; p < 8; p++) {
            int idx = tid + (p << 8);
            int r = idx >> 4, q = idx & 15;
            int tok = toks[r];
            const float* src = g_Xp + (size_t)(tok < 0 ? 0 : tok) * C + kc * 64 + q * 4;
            cpa16(aoff[b] + r * MS * 4 + q * 16, src, tok >= 0);
        }
        #pragma unroll
        for (int p = 0; p < 4; p++) {
            int idx = tid + (p << 8);
            int i = idx >> 4, q = idx & 15;
            const float* src = g_W1t + ((size_t)e * II + i) * C + kc * 64 + q * 4;
            cpa16(boff[b] + i * MS * 4 + q * 16, src, true);
        }
        CP_COMMIT();
    };

    // ---------- phase 1: H = gelu(Xg @ W1^T), warp tile 32x32 ----------
    {
        int nbase = warpN * 32;
        float d[2][4][4];
        #pragma unroll
        for (int mt = 0; mt < 2; mt++)
            #pragma unroll
            for (int nt = 0; nt < 4; nt++)
                #pragma unroll
                for (int i = 0; i < 4; i++) d[mt][nt][i] = 0.f;

        stage1(0, 0);
        #pragma unroll 1
        for (int kc = 0; kc < 8; kc++) {
            if (kc + 1 < 8) { stage1(kc + 1, (kc + 1) & 1); CP_WAIT(1); }
            else            { CP_WAIT(0); }
            __syncthreads();

            float* Ab = (float*)(smem + OFF_A0 + (kc & 1) * ABUF_B);
            float* Bb = (float*)(smem + OFF_B + (kc & 1) * (64 * MS * 4));

            #pragma unroll
            for (int ks = 0; ks < 8; ks++) {
                int k0 = ks * 8;
                uint32_t afr[2][4], bfr[4][2];
                #pragma unroll
                for (int mt = 0; mt < 2; mt++) {
                    int row = rbase + mt * 16 + lr;
                    float2 pa0 = *(float2*)(Ab + row * MS + k0 + lc * 2);
                    float2 pa1 = *(float2*)(Ab + (row + 8) * MS + k0 + lc * 2);
                    afr[mt][0] = __float_as_uint(pa0.x);
                    afr[mt][1] = __float_as_uint(pa1.x);
                    afr[mt][2] = __float_as_uint(pa0.y);
                    afr[mt][3] = __float_as_uint(pa1.y);
                }
                #pragma unroll
                for (int nt = 0; nt < 4; nt++) {
                    int col = nbase + nt * 8 + lr;
                    float2 pb = *(float2*)(Bb + col * MS + k0 + lc * 2);
                    bfr[nt][0] = __float_as_uint(pb.x);
                    bfr[nt][1] = __float_as_uint(pb.y);
                }
                #pragma unroll
                for (int mt = 0; mt < 2; mt++)
                    #pragma unroll
                    for (int nt = 0; nt < 4; nt++)
                        mma16n8k8(d[mt][nt], afr[mt], bfr[nt]);
            }
            __syncthreads();
        }

        // prefetch W2 chunk 0 (overlaps with H epilogue)
        {
            #pragma unroll
            for (int p = 0; p < 8; p++) {
                int idx = tid + (p << 8);
                int n = idx >> 4, q = idx & 15;
                const float* src = g_W2t + ((size_t)e * C + n) * II + q * 4;
                cpa16(sb + OFF_B + n * MS * 4 + q * 16, src, true);
            }
            CP_COMMIT();
        }

        // H epilogue -> As0 in permuted layout
        float* H = (float*)(smem + OFF_A0);
        int pos0 = ((lc & 1) << 2) | (lc >> 1);   // perm(2*lc)
        #pragma unroll
        for (int mt = 0; mt < 2; mt++) {
            int r0 = rbase + mt * 16 + lr;
            #pragma unroll
            for (int nt = 0; nt < 4; nt++) {
                int base = nbase + nt * 8;
                H[r0 * MS + base + pos0]           = to_tf32(gelu_exact(d[mt][nt][0]));
                H[r0 * MS + base + pos0 + 2]       = to_tf32(gelu_exact(d[mt][nt][1]));
                H[(r0 + 8) * MS + base + pos0]     = to_tf32(gelu_exact(d[mt][nt][2]));
                H[(r0 + 8) * MS + base + pos0 + 2] = to_tf32(gelu_exact(d[mt][nt][3]));
            }
        }
    }

    // ---------- phase 2: Y = H @ W2^T over 4 n-chunks, warp tile 32x64 ----------
    float* H = (float*)(smem + OFF_A0);
    uint32_t w2off[2] = { sb + OFF_B, sb + OFF_A1 };
    int nbase2 = warpN * 64;

    auto stage2 = [&](int nc, int b) {
        #pragma unroll
        for (int p = 0; p < 8; p++) {
            int idx = tid + (p << 8);
            int n = idx >> 4, q = idx & 15;
            const float* src = g_W2t + ((size_t)e * C + nc * 128 + n) * II + q * 4;
            cpa16(w2off[b] + n * MS * 4 + q * 16, src, true);
        }
        CP_COMMIT();
    };

    #pragma unroll 1
    for (int nc = 0; nc < 4; nc++) {
        if (nc + 1 < 4) { stage2(nc + 1, (nc + 1) & 1); CP_WAIT(1); }
        else            { CP_WAIT(0); }
        __syncthreads();

        float* Wb = (float*)(smem + (nc & 1 ? OFF_A1 : OFF_B));

        float d2[2][8][4];
        #pragma unroll
        for (int mt = 0; mt < 2; mt++)
            #pragma unroll
            for (int nt = 0; nt < 8; nt++)
                #pragma unroll
                for (int i = 0; i < 4; i++) d2[mt][nt][i] = 0.f;

        #pragma unroll
        for (int ks = 0; ks < 8; ks++) {
            int k0 = ks * 8;
            uint32_t afr[2][4], bfr[8][2];
            #pragma unroll
            for (int mt = 0; mt < 2; mt++) {
                int row = rbase + mt * 16 + lr;
                float2 pa0 = *(float2*)(H + row * MS + k0 + lc * 2);
                float2 pa1 = *(float2*)(H + (row + 8) * MS + k0 + lc * 2);
                afr[mt][0] = __float_as_uint(pa0.x);
                afr[mt][1] = __float_as_uint(pa1.x);
                afr[mt][2] = __float_as_uint(pa0.y);
                afr[mt][3] = __float_as_uint(pa1.y);
            }
            #pragma unroll
            for (int nt = 0; nt < 8; nt++) {
                int col = nbase2 + nt * 8 + lr;
                float2 pb = *(float2*)(Wb + col * MS + k0 + lc * 2);
                bfr[nt][0] = __float_as_uint(pb.x);
                bfr[nt][1] = __float_as_uint(pb.y);
            }
            #pragma unroll
            for (int mt = 0; mt < 2; mt++)
                #pragma unroll
                for (int nt = 0; nt < 8; nt++)
                    mma16n8k8(d2[mt][nt], afr[mt], bfr[nt]);
        }

        #pragma unroll
        for (int mt = 0; mt < 2; mt++) {
            int s0 = rbase + mt * 16 + lr, s1 = s0 + 8;
            int tok0 = toks[s0], tok1 = toks[s1];
            #pragma unroll
            for (int nt = 0; nt < 8; nt++) {
                int col = nc * 128 + nbase2 + nt * 8 + lc * 2;
                if (tok0 >= 0)
                    *(float2*)&feo[((size_t)tok0 * E + e) * C + col] =
                        make_float2(d2[mt][nt][0], d2[mt][nt][1]);
                if (tok1 >= 0)
                    *(float2*)&feo[((size_t)tok1 * E + e) * C + col] =
                        make_float2(d2[mt][nt][2], d2[mt][nt][3]);
            }
        }
        __syncthreads();
    }
}

// ---------------- final reduce: compact active list + 4 independent chains ---------
__global__ __launch_bounds__(128) void final_reduce(
    const float* __restrict__ maskp, const float* __restrict__ feo,
    float* __restrict__ final_out) {
    int t = blockIdx.x;
    int tid = threadIdx.x;
    int lane = tid & 31;
    __shared__ float s_w[E];
    __shared__ int   s_ei[E];
    __shared__ int   s_na;

    if (tid < 32) {
        float mv = maskp[(size_t)t * E + lane];
        unsigned act = __ballot_sync(FULLMASK, mv > 0.f);
        int rank = __popc(act & ((1u << lane) - 1u));
        if (mv > 0.f) {
            s_ei[rank] = lane;
            s_w[rank]  = g_rw[t * E + lane];
        }
        if (lane == 0) s_na = __popc(act);
    }
    __syncthreads();

    int na = s_na;
    const float4* base = (const float4*)&feo[(size_t)t * E * C];
    float4 a0 = make_float4(0.f, 0.f, 0.f, 0.f), a1 = a0, a2 = a0, a3 = a0;
    int i = 0;
    for (; i + 4 <= na; i += 4) {
        float w0 = s_w[i], w1 = s_w[i + 1], w2 = s_w[i + 2], w3 = s_w[i + 3];
        float4 v0 = base[s_ei[i]     * 128 + tid];
        float4 v1 = base[s_ei[i + 1] * 128 + tid];
        float4 v2 = base[s_ei[i + 2] * 128 + tid];
        float4 v3 = base[s_ei[i + 3] * 128 + tid];
        a0.x = fmaf(w0, v0.x, a0.x); a0.y = fmaf(w0, v0.y, a0.y);
        a0.z = fmaf(w0, v0.z, a0.z); a0.w = fmaf(w0, v0.w, a0.w);
        a1.x = fmaf(w1, v1.x, a1.x); a1.y = fmaf(w1, v1.y, a1.y);
        a1.z = fmaf(w1, v1.z, a1.z); a1.w = fmaf(w1, v1.w, a1.w);
        a2.x = fmaf(w2, v2.x, a2.x); a2.y = fmaf(w2, v2.y, a2.y);
        a2.z = fmaf(w2, v2.z, a2.z); a2.w = fmaf(w2, v2.w, a2.w);
        a3.x = fmaf(w3, v3.x, a3.x); a3.y = fmaf(w3, v3.y, a3.y);
        a3.z = fmaf(w3, v3.z, a3.z); a3.w = fmaf(w3, v3.w, a3.w);
    }
    for (; i < na; i++) {
        float w0 = s_w[i];
        float4 v0 = base[s_ei[i] * 128 + tid];
        a0.x = fmaf(w0, v0.x, a0.x); a0.y = fmaf(w0, v0.y, a0.y);
        a0.z = fmaf(w0, v0.z, a0.z); a0.w = fmaf(w0, v0.w, a0.w);
    }
    float4 acc;
    acc.x = (a0.x + a1.x) + (a2.x + a3.x);
    acc.y = (a0.y + a1.y) + (a2.y + a3.y);
    acc.z = (a0.z + a1.z) + (a2.z + a3.z);
    acc.w = (a0.w + a1.w) + (a2.w + a3.w);
    ((float4*)&final_out[(size_t)t * C])[tid] = acc;
}

// ---------------- launch ----------------
extern "C" void kernel_launch(void* const* d_in, const int* in_sizes, int n_in,
                              void* d_out, int out_size) {
    const float* x     = (const float*)d_in[0];
    const float* sim   = (const float*)d_in[1];
    const float* gates = (const float*)d_in[2];
    const float* W1    = (const float*)d_in[3];
    const float* W2    = (const float*)d_in[4];

    float* out       = (float*)d_out;
    float* final_out = out;
    float* feo       = out + (size_t)T * C;
    float* pre       = feo + (size_t)T * E * C;
    float* maskp     = pre + (size_t)T * E;

    cudaFuncSetAttribute(expert_mlp, cudaFuncAttributeMaxDynamicSharedMemorySize, EM_SMEM);

    prep_kernel<<<1, 1024>>>(sim, gates);
    transpose_w1<<<dim3(C / 32, II / 32, E), 256>>>(W1);
    transpose_w2<<<dim3(II / 32, C / 32, E), 256>>>(W2);
    round_x<<<T, 128>>>(x);
    gating_kernel<<<T / 8, 256>>>(x, sim, pre, maskp);
    expert_mlp<<<dim3(T / 128 + 1, E), 256, EM_SMEM>>>(feo);
    final_reduce<<<T, 128>>>(maskp, feo, final_out);
}